// round 13
// baseline (speedup 1.0000x reference)
#include <cuda_runtime.h>
#include <cstdint>

// ---------------------------------------------------------------------------
// Arch gate: tcgen05 only exists on the arch-specific (sm_103a) target. The
// harness also compiles a plain compute_103 target, which must fall back.
// ---------------------------------------------------------------------------
#if defined(__CUDA_ARCH_FEAT_SM103_ALL) || defined(__CUDA_ARCH_FEAT_SM100_ALL) || \
    defined(__CUDA_ARCH_SPECIFIC__) || defined(__CUDA_ARCH_FAMILY_SPECIFIC__)
#define USE_TC 1
#else
#define USE_TC 0
#endif

// ---------------------------------------------------------------------------
// Problem constants
// ---------------------------------------------------------------------------
constexpr int Pn   = 48 * 48;   // 2304
constexpr int CX_  = 512;
constexpr int CF_  = 256;
constexpr int HID_ = 256;
constexpr int OUT_ = 512;
constexpr int BN_  = 16;

// ---------------------------------------------------------------------------
// Scratch (device globals; no allocation allowed). Everything K-major for its
// consumer GEMM.
// ---------------------------------------------------------------------------
__device__ float g_mvT[(size_t)BN_ * Pn * CX_];   // [z][p][cx]
__device__ float g_ffT[(size_t)4   * Pn * CF_];   // [b][p][cf]
__device__ float g_Q1t[(size_t)BN_ * Pn * HID_];  // [z][p][h]
__device__ float g_K1t[(size_t)4   * Pn * HID_];
__device__ float g_Q2t[(size_t)4   * Pn * HID_];
__device__ float g_K2t[(size_t)BN_ * Pn * HID_];
__device__ float g_S  [(size_t)BN_ * Pn * Pn];    // scores/attn (both layers)
__device__ float g_WRT[(size_t)BN_ * Pn * CF_];   // [z][p][cf]
__device__ float g_WLT[(size_t)BN_ * Pn * CX_];   // [z][p][cx]

// ---------------------------------------------------------------------------
// PTX helpers
// ---------------------------------------------------------------------------
__device__ __forceinline__ uint32_t smem_u32(const void* p) {
    uint32_t a;
    asm("{ .reg .u64 t; cvta.to.shared.u64 t, %1; cvt.u32.u64 %0, t; }"
        : "=r"(a) : "l"(p));
    return a;
}
// Bitmask hi/lo split: hi keeps the top 10 mantissa bits (tf32-exact), lo is
// the exact residual; lo's own tf32 truncation leaves ~2^-23 relative error.
__device__ __forceinline__ void split2(float x, float& hi, float& lo) {
    hi = __uint_as_float(__float_as_uint(x) & 0xffffe000u);
    lo = x - hi;
}

#define MBAR_INIT(a, c) \
    asm volatile("mbarrier.init.shared.b64 [%0], %1;" :: "r"(a), "r"(c) : "memory")
#define MBAR_WAIT(a, ph) do {                                                  \
    uint32_t _m = (a), _p = (ph), _d = 0;                                      \
    while (!_d) {                                                              \
        asm volatile("{\n\t.reg .pred p;\n\t"                                  \
            "mbarrier.try_wait.parity.acquire.cta.shared::cta.b64 p, [%1], %2, 0x989680;\n\t" \
            "selp.b32 %0, 1, 0, p;\n\t}"                                       \
            : "=r"(_d) : "r"(_m), "r"(_p) : "memory");                         \
    } } while (0)

#define TC_ALLOC(sa, nc) \
    asm volatile("tcgen05.alloc.cta_group::1.sync.aligned.shared::cta.b32 [%0], %1;" \
        :: "r"(sa), "r"((uint32_t)(nc)) : "memory")
#define TC_RELINQ() \
    asm volatile("tcgen05.relinquish_alloc_permit.cta_group::1.sync.aligned;")
#define TC_DEALLOC(tm, nc) \
    asm volatile("tcgen05.dealloc.cta_group::1.sync.aligned.b32 %0, %1;" \
        :: "r"(tm), "r"((uint32_t)(nc)))
#define TC_COMMIT(mb) \
    asm volatile("tcgen05.commit.cta_group::1.mbarrier::arrive::one.shared::cluster.b64 [%0];" \
        :: "r"(mb) : "memory")
#define TC_FENCE_AFTER()  asm volatile("tcgen05.fence::after_thread_sync;" ::: "memory")
#define TC_FENCE_BEFORE() asm volatile("tcgen05.fence::before_thread_sync;" ::: "memory")
#define TC_WAIT_LD()      asm volatile("tcgen05.wait::ld.sync.aligned;" ::: "memory")
#define FENCE_ASYNC()     asm volatile("fence.proxy.async.shared::cta;" ::: "memory")

#define TC_LD_X32(r, ta) \
    asm volatile("tcgen05.ld.sync.aligned.32x32b.x32.b32 " \
        "{%0,%1,%2,%3,%4,%5,%6,%7,%8,%9,%10,%11,%12,%13,%14,%15," \
        "%16,%17,%18,%19,%20,%21,%22,%23,%24,%25,%26,%27,%28,%29,%30,%31}, [%32];" \
        : "=r"((r)[0]),"=r"((r)[1]),"=r"((r)[2]),"=r"((r)[3]),   \
          "=r"((r)[4]),"=r"((r)[5]),"=r"((r)[6]),"=r"((r)[7]),   \
          "=r"((r)[8]),"=r"((r)[9]),"=r"((r)[10]),"=r"((r)[11]), \
          "=r"((r)[12]),"=r"((r)[13]),"=r"((r)[14]),"=r"((r)[15]),\
          "=r"((r)[16]),"=r"((r)[17]),"=r"((r)[18]),"=r"((r)[19]),\
          "=r"((r)[20]),"=r"((r)[21]),"=r"((r)[22]),"=r"((r)[23]),\
          "=r"((r)[24]),"=r"((r)[25]),"=r"((r)[26]),"=r"((r)[27]),\
          "=r"((r)[28]),"=r"((r)[29]),"=r"((r)[30]),"=r"((r)[31]) \
        : "r"(ta))

// idesc: D=F32(1<<4), A=TF32(2<<7), B=TF32(2<<10), N=128 (N/8 @17), M=128 (M/16 @24)
constexpr uint32_t IDESC_TF32 =
    (1u << 4) | (2u << 7) | (2u << 10) | ((128u / 8) << 17) | ((128u / 16) << 24);

__device__ __forceinline__ void mma_tf32(uint32_t d, uint64_t ad, uint64_t bd, bool acc) {
    asm volatile("{\n\t.reg .pred p;\n\tsetp.ne.u32 p, %5, 0;\n\t"
        "tcgen05.mma.cta_group::1.kind::tf32 [%0], %1, %2, %3, {%4,%4,%4,%4}, p;\n\t}"
        :: "r"(d), "l"(ad), "l"(bd), "r"(IDESC_TF32), "r"(0u), "r"(acc ? 1u : 0u)
        : "memory");
}

// SW128 K-major smem descriptor: layout=2, version=1, SBO=64, LBO=1
constexpr uint64_t DESC_BASE =
    (2ull << 61) | (1ull << 46) | (64ull << 32) | (1ull << 16);
__device__ __forceinline__ uint64_t sdesc(uint32_t addr) {
    return DESC_BASE | ((uint64_t)(addr >> 4) & 0x3FFFull);
}
__device__ __forceinline__ uint32_t sw128(uint32_t off) {
    return off ^ ((off >> 3) & 0x70);
}

// smem: 64B header (tmem ptr @0; stage-done mbar[s] @8+8s; tile-done @40,48),
// then 1024-aligned data: 3 stages x 64KB (Ahi|Alo|Bhi|Blo 16KB each).
constexpr int TILE_B    = 16384;
constexpr int STAGE_B   = 4 * TILE_B;
constexpr int NSTAGE    = 3;
constexpr int SMEM_DYN  = 1024 + NSTAGE * STAGE_B + 1024;

// ---------------------------------------------------------------------------
// Persistent batched GEMM: D[m,n] = sum_k A[m,k] * B[n,k]; A,B K-major.
// Tiles 128x128 enumerated (z, y, x); each CTA loops tiles with stride grid.
// TMEM ping-pong (2 x 128 cols): tile i accumulates into D[i&1]; epilogue of
// tile i runs after 2 chunks of tile i+1 are queued, overlapping MMA work.
// BIASM: 0 none, 1 bias[n], 2 bias[m].
// CONV: B rows gathered from concat(Bg=mvT | Bc1=WLT | Bc2=ffT | Bc3=WRT).
// ---------------------------------------------------------------------------
template<int BIASM, bool CONV>
__global__ void __launch_bounds__(256, 1)
tfgemm(const float* __restrict__ Ag, int lda, long long sA, int dA,
       const float* __restrict__ Bg, int ldb, long long sB, int dB,
       const float* __restrict__ Bc1, const float* __restrict__ Bc2,
       const float* __restrict__ Bc3,
       const float* __restrict__ bias,
       float* __restrict__ Cg, int ldc, long long sC, int K,
       int ntx, int nty, int ntotal)
{
    extern __shared__ char smem[];
    const int tid  = threadIdx.x;

    const uint32_t sbase = smem_u32(smem);
    const uint32_t data  = (sbase + 64 + 1023) & ~1023u;
    char* dptr = smem + (data - sbase);

    const int nk = K >> 5;

    auto bsel = [&](int z, int kc, const float*& bp, int& bld, int& bkc) {
        if (!CONV) {
            bp = Bg + (long long)(z / dB) * sB; bld = ldb; bkc = kc;
        } else {
            if      (kc < 512)  { bp = Bg  + (long long)z * ((long long)Pn * 512);        bld = 512; bkc = kc; }
            else if (kc < 1024) { bp = Bc1 + (long long)z * ((long long)Pn * 512);        bld = 512; bkc = kc - 512; }
            else if (kc < 1280) { bp = Bc2 + (long long)(z >> 2) * ((long long)Pn * 256); bld = 256; bkc = kc - 1024; }
            else                { bp = Bc3 + (long long)z * ((long long)Pn * 256);        bld = 256; bkc = kc - 1280; }
        }
    };

#if USE_TC
    // ======================= tcgen05 fast path (sm_103a) ====================
    const int wid  = tid >> 5;
    const int lane = tid & 31;
    const uint32_t hdr    = sbase;
    const uint32_t done0  = hdr + 8;    // 3 stage mbarriers
    const uint32_t tdone0 = hdr + 40;   // 2 tile-done mbarriers

    if (wid == 0) { TC_ALLOC(hdr, 256); TC_RELINQ(); }
    if (tid == 0) {
        #pragma unroll
        for (int s = 0; s < NSTAGE; ++s) MBAR_INIT(done0 + 8u * s, 1);
        MBAR_INIT(tdone0, 1);
        MBAR_INIT(tdone0 + 8, 1);
    }
    __syncthreads();
    uint32_t tmem;
    asm volatile("ld.shared.b32 %0, [%1];" : "=r"(tmem) : "r"(hdr));

    // chunk-invariant producer indexing
    const int c4 = tid & 7;
    const int r0 = tid >> 3;
    uint32_t soff[4];
    #pragma unroll
    for (int i = 0; i < 4; ++i)
        soff[i] = sw128((uint32_t)((r0 + i * 32) * 128 + c4 * 16));

    // epilogue indexing
    const int rsub = (wid & 3) * 32 + lane;
    const int g0   = (wid >> 2) * 2;

    // pending-epilogue state
    int   pend     = 0;          // 0 = none
    int   pm0 = 0, pn0 = 0;
    float* pC      = nullptr;
    uint32_t pdbuf = 0, pmb = 0;
    int   pph      = 0;

    auto epilogue = [&]() {
        MBAR_WAIT(pmb, pph);
        TC_FENCE_AFTER();
        #pragma unroll
        for (int gi = 0; gi < 2; ++gi) {
            const int g = g0 + gi;
            uint32_t r[32];
            TC_LD_X32(r, pdbuf + g * 32);
            TC_WAIT_LD();
            float rowb = (BIASM == 2) ? bias[pm0 + rsub] : 0.0f;
            float* crow = pC + (size_t)(pm0 + rsub) * ldc + pn0 + g * 32;
            #pragma unroll
            for (int cc = 0; cc < 8; ++cc) {
                float4 v;
                v.x = __uint_as_float(r[cc * 4 + 0]);
                v.y = __uint_as_float(r[cc * 4 + 1]);
                v.z = __uint_as_float(r[cc * 4 + 2]);
                v.w = __uint_as_float(r[cc * 4 + 3]);
                if (BIASM == 1) {
                    float4 bv = *reinterpret_cast<const float4*>(bias + pn0 + g * 32 + cc * 4);
                    v.x += bv.x; v.y += bv.y; v.z += bv.z; v.w += bv.w;
                } else if (BIASM == 2) {
                    v.x += rowb; v.y += rowb; v.z += rowb; v.w += rowb;
                }
                *reinterpret_cast<float4*>(crow + cc * 4) = v;
            }
        }
        TC_FENCE_BEFORE();
        pend = 0;
    };

    int gc = 0;   // global chunk counter (stage-recycle phase tracking)
    int it = 0;   // tile iteration counter

    for (int t = blockIdx.x; t < ntotal; t += gridDim.x, ++it) {
        const int z  = t / (ntx * nty);
        const int rm = t - z * (ntx * nty);
        const int m0 = (rm / ntx) * 128;
        const int n0 = (rm - (rm / ntx) * ntx) * 128;

        const float* aptr = Ag + (long long)(z / dA) * sA
                          + (size_t)(m0 + r0) * lda + c4 * 4;
        const size_t astr = (size_t)32 * lda;
        const float* bptr0 = nullptr;
        size_t bstr = 0;
        if (!CONV) {
            bptr0 = Bg + (long long)(z / dB) * sB + (size_t)(n0 + r0) * ldb + c4 * 4;
            bstr  = (size_t)32 * ldb;
        }
        const uint32_t dbuf = tmem + (uint32_t)((it & 1) * 128);

        for (int ch = 0; ch < nk; ++ch) {
            const int kc = ch << 5;

            // issue gmem loads before the stage-recycle wait
            float4 va[4], vb[4];
            #pragma unroll
            for (int i = 0; i < 4; ++i)
                va[i] = *reinterpret_cast<const float4*>(aptr + kc + (size_t)i * astr);
            if (!CONV) {
                #pragma unroll
                for (int i = 0; i < 4; ++i)
                    vb[i] = *reinterpret_cast<const float4*>(bptr0 + kc + (size_t)i * bstr);
            } else {
                const float* bp; int bld, bkc;
                bsel(z, kc, bp, bld, bkc);
                const float* bt = bp + (size_t)(n0 + r0) * bld + bkc + c4 * 4;
                #pragma unroll
                for (int i = 0; i < 4; ++i)
                    vb[i] = *reinterpret_cast<const float4*>(bt + (size_t)i * 32 * bld);
            }

            const int ps = gc % NSTAGE;
            const int rr = gc / NSTAGE;
            if (rr > 0) MBAR_WAIT(done0 + 8u * ps, (rr - 1) & 1);

            char* stg = dptr + ps * STAGE_B;
            #pragma unroll
            for (int i = 0; i < 4; ++i) {
                float4 hi, lo;
                split2(va[i].x, hi.x, lo.x); split2(va[i].y, hi.y, lo.y);
                split2(va[i].z, hi.z, lo.z); split2(va[i].w, hi.w, lo.w);
                *reinterpret_cast<float4*>(stg + soff[i])          = hi;
                *reinterpret_cast<float4*>(stg + TILE_B + soff[i]) = lo;
            }
            #pragma unroll
            for (int i = 0; i < 4; ++i) {
                float4 hi, lo;
                split2(vb[i].x, hi.x, lo.x); split2(vb[i].y, hi.y, lo.y);
                split2(vb[i].z, hi.z, lo.z); split2(vb[i].w, hi.w, lo.w);
                *reinterpret_cast<float4*>(stg + 2 * TILE_B + soff[i]) = hi;
                *reinterpret_cast<float4*>(stg + 3 * TILE_B + soff[i]) = lo;
            }

            __syncthreads();

            if (tid == 0) {
                FENCE_ASYNC();
                uint32_t sb = data + ps * STAGE_B;
                uint64_t ah = sdesc(sb);
                uint64_t al = sdesc(sb + TILE_B);
                uint64_t bh = sdesc(sb + 2 * TILE_B);
                uint64_t bl = sdesc(sb + 3 * TILE_B);
                #pragma unroll
                for (int ks = 0; ks < 4; ++ks) {
                    uint64_t o = (uint64_t)(ks * 2);
                    mma_tf32(dbuf, ah + o, bh + o, !(ch == 0 && ks == 0));
                    mma_tf32(dbuf, ah + o, bl + o, true);
                    mma_tf32(dbuf, al + o, bh + o, true);
                }
                TC_COMMIT(done0 + 8u * ps);
                if (ch == nk - 1) TC_COMMIT(tdone0 + 8u * (it & 1));
            }
            ++gc;

            // run deferred epilogue once 2 chunks of this tile are queued
            if (ch == 1 && pend) epilogue();
        }
        if (pend) epilogue();   // safety for nk < 2 (not hit here)

        pend  = 1;
        pm0   = m0; pn0 = n0;
        pC    = Cg + (long long)z * sC;
        pdbuf = dbuf;
        pmb   = tdone0 + 8u * (it & 1);
        pph   = (it >> 1) & 1;
    }
    if (pend) epilogue();

    __syncthreads();
    if (wid == 0) TC_DEALLOC(tmem, 256);

#else
    // ================== portable FFMA fallback (plain sm_103) ===============
    float* As2 = reinterpret_cast<float*>(dptr);
    float* Bs2 = As2 + 32 * 128;
    const int tx = tid & 15, ty = tid >> 4;

    for (int t = blockIdx.x; t < ntotal; t += gridDim.x) {
        const int z  = t / (ntx * nty);
        const int rm = t - z * (ntx * nty);
        const int m0 = (rm / ntx) * 128;
        const int n0 = (rm - (rm / ntx) * ntx) * 128;
        const float* A = Ag + (long long)(z / dA) * sA;

        float acc[8][8];
        #pragma unroll
        for (int i = 0; i < 8; ++i)
            #pragma unroll
            for (int j = 0; j < 8; ++j) acc[i][j] = 0.0f;

        for (int ch = 0; ch < nk; ++ch) {
            const int kc = ch << 5;
            __syncthreads();
            #pragma unroll
            for (int i = 0; i < 4; ++i) {
                int u = tid + i * 256;
                int row = u >> 3, cc = u & 7;
                float4 v = *reinterpret_cast<const float4*>(
                    A + (size_t)(m0 + row) * lda + kc + cc * 4);
                As2[(cc * 4 + 0) * 128 + row] = v.x;
                As2[(cc * 4 + 1) * 128 + row] = v.y;
                As2[(cc * 4 + 2) * 128 + row] = v.z;
                As2[(cc * 4 + 3) * 128 + row] = v.w;
            }
            const float* bp; int bld, bkc;
            bsel(z, kc, bp, bld, bkc);
            #pragma unroll
            for (int i = 0; i < 4; ++i) {
                int u = tid + i * 256;
                int row = u >> 3, cc = u & 7;
                float4 v = *reinterpret_cast<const float4*>(
                    bp + (size_t)(n0 + row) * bld + bkc + cc * 4);
                Bs2[(cc * 4 + 0) * 128 + row] = v.x;
                Bs2[(cc * 4 + 1) * 128 + row] = v.y;
                Bs2[(cc * 4 + 2) * 128 + row] = v.z;
                Bs2[(cc * 4 + 3) * 128 + row] = v.w;
            }
            __syncthreads();
            #pragma unroll
            for (int kk = 0; kk < 32; ++kk) {
                float a[8], b[8];
                #pragma unroll
                for (int i = 0; i < 4; ++i) {
                    a[i]     = As2[kk * 128 + ty * 4 + i];
                    a[i + 4] = As2[kk * 128 + 64 + ty * 4 + i];
                    b[i]     = Bs2[kk * 128 + tx * 4 + i];
                    b[i + 4] = Bs2[kk * 128 + 64 + tx * 4 + i];
                }
                #pragma unroll
                for (int i = 0; i < 8; ++i)
                    #pragma unroll
                    for (int j = 0; j < 8; ++j)
                        acc[i][j] = fmaf(a[i], b[j], acc[i][j]);
            }
        }

        float* C = Cg + (long long)z * sC;
        #pragma unroll
        for (int i = 0; i < 8; ++i) {
            const int m = m0 + ((i < 4) ? (ty * 4 + i) : (64 + ty * 4 + i - 4));
            const float rowb = (BIASM == 2) ? bias[m] : 0.0f;
            #pragma unroll
            for (int jh = 0; jh < 2; ++jh) {
                const int n = n0 + jh * 64 + tx * 4;
                float4 v;
                v.x = acc[i][jh * 4 + 0]; v.y = acc[i][jh * 4 + 1];
                v.z = acc[i][jh * 4 + 2]; v.w = acc[i][jh * 4 + 3];
                if (BIASM == 1) {
                    float4 bv = *reinterpret_cast<const float4*>(bias + n);
                    v.x += bv.x; v.y += bv.y; v.z += bv.z; v.w += bv.w;
                } else if (BIASM == 2) {
                    v.x += rowb; v.y += rowb; v.z += rowb; v.w += rowb;
                }
                *reinterpret_cast<float4*>(C + (size_t)m * ldc + n) = v;
            }
        }
        __syncthreads();
    }
#endif
}

// ---------------------------------------------------------------------------
// 32x32 tiled transpose: src [z][C][Pn] -> dst [z][Pn][C]
// ---------------------------------------------------------------------------
__global__ void __launch_bounds__(256)
transp(const float* __restrict__ src, float* __restrict__ dst, int C)
{
    __shared__ float tile[32][33];
    const int p0 = blockIdx.x * 32, c0 = blockIdx.y * 32;
    const float* s = src + (size_t)blockIdx.z * C * Pn;
    float*       d = dst + (size_t)blockIdx.z * C * Pn;
    #pragma unroll
    for (int j = 0; j < 32; j += 8)
        tile[threadIdx.y + j][threadIdx.x] =
            s[(size_t)(c0 + threadIdx.y + j) * Pn + p0 + threadIdx.x];
    __syncthreads();
    #pragma unroll
    for (int j = 0; j < 32; j += 8)
        d[(size_t)(p0 + threadIdx.y + j) * C + c0 + threadIdx.x] =
            tile[threadIdx.x][threadIdx.y + j];
}

// ---------------------------------------------------------------------------
// Row softmax over g_S: grid (Pn, BN_), 256 threads, 9 elems/thread in regs
// ---------------------------------------------------------------------------
__global__ __launch_bounds__(256)
void softmax_rows(float* __restrict__ S)
{
    const int tid = threadIdx.x;
    const size_t base = ((size_t)blockIdx.y * Pn + blockIdx.x) * Pn;

    float r[9];
    float mx = -3.4e38f;
    #pragma unroll
    for (int j = 0; j < 9; ++j) {
        r[j] = S[base + tid + j * 256];
        mx = fmaxf(mx, r[j]);
    }
    __shared__ float sred[8];
    #pragma unroll
    for (int o = 16; o > 0; o >>= 1)
        mx = fmaxf(mx, __shfl_xor_sync(0xffffffffu, mx, o));
    if ((tid & 31) == 0) sred[tid >> 5] = mx;
    __syncthreads();
    mx = sred[0];
    #pragma unroll
    for (int w = 1; w < 8; ++w) mx = fmaxf(mx, sred[w]);

    float s = 0.0f;
    #pragma unroll
    for (int j = 0; j < 9; ++j) { r[j] = __expf(r[j] - mx); s += r[j]; }
    #pragma unroll
    for (int o = 16; o > 0; o >>= 1)
        s += __shfl_xor_sync(0xffffffffu, s, o);
    __syncthreads();
    if ((tid & 31) == 0) sred[tid >> 5] = s;
    __syncthreads();
    s = 0.0f;
    #pragma unroll
    for (int w = 0; w < 8; ++w) s += sred[w];

    const float inv = 1.0f / s;
    #pragma unroll
    for (int j = 0; j < 9; ++j)
        S[base + tid + j * 256] = r[j] * inv;
}

// ---------------------------------------------------------------------------
// Launch sequence (default stream, graph-capturable)
// ---------------------------------------------------------------------------
static inline int pgrid(int total) { return total < 148 ? total : 148; }

extern "C" void kernel_launch(void* const* d_in, const int* in_sizes, int n_in,
                              void* d_out, int out_size)
{
    const float* mv  = (const float*)d_in[0];   // [16,512,P]
    const float* ff  = (const float*)d_in[1];   // [4,256,P]
    const float* wq1 = (const float*)d_in[2];
    const float* bq1 = (const float*)d_in[3];
    const float* wk1 = (const float*)d_in[4];
    const float* bk1 = (const float*)d_in[5];
    const float* wq2 = (const float*)d_in[6];
    const float* bq2 = (const float*)d_in[7];
    const float* wk2 = (const float*)d_in[8];
    const float* bk2 = (const float*)d_in[9];
    const float* wdr = (const float*)d_in[10];  // [512,1536]
    const float* bdr = (const float*)d_in[11];
    float* out = (float*)d_out;                 // [16,512,P]

    float *mvT, *ffT, *Q1t, *K1t, *Q2t, *K2t, *S, *WRT, *WLT;
    cudaGetSymbolAddress((void**)&mvT, g_mvT);
    cudaGetSymbolAddress((void**)&ffT, g_ffT);
    cudaGetSymbolAddress((void**)&Q1t, g_Q1t);
    cudaGetSymbolAddress((void**)&K1t, g_K1t);
    cudaGetSymbolAddress((void**)&Q2t, g_Q2t);
    cudaGetSymbolAddress((void**)&K2t, g_K2t);
    cudaGetSymbolAddress((void**)&S,   g_S);
    cudaGetSymbolAddress((void**)&WRT, g_WRT);
    cudaGetSymbolAddress((void**)&WLT, g_WLT);

    cudaFuncSetAttribute(tfgemm<0, false>, cudaFuncAttributeMaxDynamicSharedMemorySize, SMEM_DYN);
    cudaFuncSetAttribute(tfgemm<1, false>, cudaFuncAttributeMaxDynamicSharedMemorySize, SMEM_DYN);
    cudaFuncSetAttribute(tfgemm<2, true>,  cudaFuncAttributeMaxDynamicSharedMemorySize, SMEM_DYN);

    const long long sMVT = (long long)Pn * CX_;
    const long long sFFT = (long long)Pn * CF_;
    const long long sHT  = (long long)Pn * HID_;
    const long long sS   = (long long)Pn * Pn;
    const long long sWRT = (long long)Pn * CF_;
    const long long sWLT = (long long)Pn * CX_;
    const long long sO   = (long long)OUT_ * Pn;

    // transposes -> K-major inputs
    transp<<<dim3(Pn / 32, CX_ / 32, 16), dim3(32, 8)>>>(mv, mvT, CX_);
    transp<<<dim3(Pn / 32, CF_ / 32, 4),  dim3(32, 8)>>>(ff, ffT, CF_);

    // projections: D[p,h] = sum_c X[p,c] * W[h,c] + b[h]   (ntx=2, nty=18)
    tfgemm<1, false><<<pgrid(2 * 18 * 16), 256, SMEM_DYN>>>(
        mvT, CX_, sMVT, 1,  wq1, CX_, 0LL, 1,  nullptr, nullptr, nullptr,
        bq1,  Q1t, HID_, sHT, CX_,  2, 18, 2 * 18 * 16);
    tfgemm<1, false><<<pgrid(2 * 18 * 4), 256, SMEM_DYN>>>(
        ffT, CF_, sFFT, 1,  wk1, CF_, 0LL, 1,  nullptr, nullptr, nullptr,
        bk1,  K1t, HID_, sHT, CF_,  2, 18, 2 * 18 * 4);
    tfgemm<1, false><<<pgrid(2 * 18 * 4), 256, SMEM_DYN>>>(
        ffT, CF_, sFFT, 1,  wq2, CF_, 0LL, 1,  nullptr, nullptr, nullptr,
        bq2,  Q2t, HID_, sHT, CF_,  2, 18, 2 * 18 * 4);
    tfgemm<1, false><<<pgrid(2 * 18 * 16), 256, SMEM_DYN>>>(
        mvT, CX_, sMVT, 1,  wk2, CX_, 0LL, 1,  nullptr, nullptr, nullptr,
        bk2,  K2t, HID_, sHT, CX_,  2, 18, 2 * 18 * 16);

    // layer 1: S[p,q] = Q1t[p,:].K1t[q,:]; softmax; WRT[p,c] = S[p,:].ff[c,:]
    tfgemm<0, false><<<pgrid(18 * 18 * 16), 256, SMEM_DYN>>>(
        Q1t, HID_, sHT, 1,  K1t, HID_, sHT, 4,  nullptr, nullptr, nullptr,
        nullptr,  S, Pn, sS, HID_,  18, 18, 18 * 18 * 16);
    softmax_rows<<<dim3(Pn, BN_), 256>>>(S);
    tfgemm<0, false><<<pgrid(2 * 18 * 16), 256, SMEM_DYN>>>(
        S, Pn, sS, 1,  ff, Pn, (long long)CF_ * Pn, 4,  nullptr, nullptr, nullptr,
        nullptr,  WRT, CF_, sWRT, Pn,  2, 18, 2 * 18 * 16);

    // layer 2
    tfgemm<0, false><<<pgrid(18 * 18 * 16), 256, SMEM_DYN>>>(
        Q2t, HID_, sHT, 4,  K2t, HID_, sHT, 1,  nullptr, nullptr, nullptr,
        nullptr,  S, Pn, sS, HID_,  18, 18, 18 * 18 * 16);
    softmax_rows<<<dim3(Pn, BN_), 256>>>(S);
    tfgemm<0, false><<<pgrid(4 * 18 * 16), 256, SMEM_DYN>>>(
        S, Pn, sS, 1,  mv, Pn, (long long)CX_ * Pn, 1,  nullptr, nullptr, nullptr,
        nullptr,  WLT, CX_, sWLT, Pn,  4, 18, 4 * 18 * 16);

    // fused conv: out[o,p] = sum_f wdr[o,f] * featT[p,f] + bdr[o], K=1536
    tfgemm<2, true><<<pgrid(18 * 4 * 16), 256, SMEM_DYN>>>(
        wdr, 1536, 0LL, 1,  mvT, 0, 0LL, 1,  WLT, ffT, WRT,
        bdr,  out, Pn, sO, 1536,  18, 4, 18 * 4 * 16);
}

// round 14
// speedup vs baseline: 1.2901x; 1.2901x over previous
#include <cuda_runtime.h>
#include <cstdint>

// ---------------------------------------------------------------------------
// Arch gate: tcgen05 only exists on the arch-specific (sm_103a) target. The
// harness also compiles a plain compute_103 target, which must fall back.
// ---------------------------------------------------------------------------
#if defined(__CUDA_ARCH_FEAT_SM103_ALL) || defined(__CUDA_ARCH_FEAT_SM100_ALL) || \
    defined(__CUDA_ARCH_SPECIFIC__) || defined(__CUDA_ARCH_FAMILY_SPECIFIC__)
#define USE_TC 1
#else
#define USE_TC 0
#endif

// ---------------------------------------------------------------------------
// Problem constants
// ---------------------------------------------------------------------------
constexpr int Pn   = 48 * 48;   // 2304
constexpr int CX_  = 512;
constexpr int CF_  = 256;
constexpr int HID_ = 256;
constexpr int OUT_ = 512;
constexpr int BN_  = 16;

// ---------------------------------------------------------------------------
// Scratch (device globals; no allocation allowed). Everything K-major for its
// consumer GEMM.
// ---------------------------------------------------------------------------
__device__ float g_mvT[(size_t)BN_ * Pn * CX_];   // [z][p][cx]
__device__ float g_ffT[(size_t)4   * Pn * CF_];   // [b][p][cf]
__device__ float g_Q1t[(size_t)BN_ * Pn * HID_];  // [z][p][h]
__device__ float g_K1t[(size_t)4   * Pn * HID_];
__device__ float g_Q2t[(size_t)4   * Pn * HID_];
__device__ float g_K2t[(size_t)BN_ * Pn * HID_];
__device__ float g_S  [(size_t)BN_ * Pn * Pn];    // scores/attn (both layers)
__device__ float g_WRT[(size_t)BN_ * Pn * CF_];   // [z][p][cf]
__device__ float g_WLT[(size_t)BN_ * Pn * CX_];   // [z][p][cx]

// ---------------------------------------------------------------------------
// PTX helpers
// ---------------------------------------------------------------------------
__device__ __forceinline__ uint32_t smem_u32(const void* p) {
    uint32_t a;
    asm("{ .reg .u64 t; cvta.to.shared.u64 t, %1; cvt.u32.u64 %0, t; }"
        : "=r"(a) : "l"(p));
    return a;
}
// Bitmask hi/lo split: hi keeps the top 10 mantissa bits (tf32-exact), lo is
// the exact residual; lo's own tf32 truncation leaves ~2^-23 relative error.
__device__ __forceinline__ void split2(float x, float& hi, float& lo) {
    hi = __uint_as_float(__float_as_uint(x) & 0xffffe000u);
    lo = x - hi;
}

#define MBAR_INIT(a, c) \
    asm volatile("mbarrier.init.shared.b64 [%0], %1;" :: "r"(a), "r"(c) : "memory")
#define MBAR_WAIT(a, ph) do {                                                  \
    uint32_t _m = (a), _p = (ph), _d = 0;                                      \
    while (!_d) {                                                              \
        asm volatile("{\n\t.reg .pred p;\n\t"                                  \
            "mbarrier.try_wait.parity.acquire.cta.shared::cta.b64 p, [%1], %2, 0x989680;\n\t" \
            "selp.b32 %0, 1, 0, p;\n\t}"                                       \
            : "=r"(_d) : "r"(_m), "r"(_p) : "memory");                         \
    } } while (0)

#define TC_ALLOC(sa, nc) \
    asm volatile("tcgen05.alloc.cta_group::1.sync.aligned.shared::cta.b32 [%0], %1;" \
        :: "r"(sa), "r"((uint32_t)(nc)) : "memory")
#define TC_RELINQ() \
    asm volatile("tcgen05.relinquish_alloc_permit.cta_group::1.sync.aligned;")
#define TC_DEALLOC(tm, nc) \
    asm volatile("tcgen05.dealloc.cta_group::1.sync.aligned.b32 %0, %1;" \
        :: "r"(tm), "r"((uint32_t)(nc)))
#define TC_COMMIT(mb) \
    asm volatile("tcgen05.commit.cta_group::1.mbarrier::arrive::one.shared::cluster.b64 [%0];" \
        :: "r"(mb) : "memory")
#define TC_FENCE_AFTER() asm volatile("tcgen05.fence::after_thread_sync;" ::: "memory")
#define TC_WAIT_LD()     asm volatile("tcgen05.wait::ld.sync.aligned;" ::: "memory")
#define FENCE_ASYNC()    asm volatile("fence.proxy.async.shared::cta;" ::: "memory")

#define TC_LD_X32(r, ta) \
    asm volatile("tcgen05.ld.sync.aligned.32x32b.x32.b32 " \
        "{%0,%1,%2,%3,%4,%5,%6,%7,%8,%9,%10,%11,%12,%13,%14,%15," \
        "%16,%17,%18,%19,%20,%21,%22,%23,%24,%25,%26,%27,%28,%29,%30,%31}, [%32];" \
        : "=r"((r)[0]),"=r"((r)[1]),"=r"((r)[2]),"=r"((r)[3]),   \
          "=r"((r)[4]),"=r"((r)[5]),"=r"((r)[6]),"=r"((r)[7]),   \
          "=r"((r)[8]),"=r"((r)[9]),"=r"((r)[10]),"=r"((r)[11]), \
          "=r"((r)[12]),"=r"((r)[13]),"=r"((r)[14]),"=r"((r)[15]),\
          "=r"((r)[16]),"=r"((r)[17]),"=r"((r)[18]),"=r"((r)[19]),\
          "=r"((r)[20]),"=r"((r)[21]),"=r"((r)[22]),"=r"((r)[23]),\
          "=r"((r)[24]),"=r"((r)[25]),"=r"((r)[26]),"=r"((r)[27]),\
          "=r"((r)[28]),"=r"((r)[29]),"=r"((r)[30]),"=r"((r)[31]) \
        : "r"(ta))

// idesc: D=F32(1<<4), A=TF32(2<<7), B=TF32(2<<10), N=128 (N/8 @17), M=128 (M/16 @24)
constexpr uint32_t IDESC_TF32 =
    (1u << 4) | (2u << 7) | (2u << 10) | ((128u / 8) << 17) | ((128u / 16) << 24);

__device__ __forceinline__ void mma_tf32(uint32_t d, uint64_t ad, uint64_t bd, bool acc) {
    asm volatile("{\n\t.reg .pred p;\n\tsetp.ne.u32 p, %5, 0;\n\t"
        "tcgen05.mma.cta_group::1.kind::tf32 [%0], %1, %2, %3, {%4,%4,%4,%4}, p;\n\t}"
        :: "r"(d), "l"(ad), "l"(bd), "r"(IDESC_TF32), "r"(0u), "r"(acc ? 1u : 0u)
        : "memory");
}

// SW128 K-major smem descriptor: layout=2, version=1, SBO=64, LBO=1
constexpr uint64_t DESC_BASE =
    (2ull << 61) | (1ull << 46) | (64ull << 32) | (1ull << 16);
__device__ __forceinline__ uint64_t sdesc(uint32_t addr) {
    return DESC_BASE | ((uint64_t)(addr >> 4) & 0x3FFFull);
}
__device__ __forceinline__ uint32_t sw128(uint32_t off) {
    return off ^ ((off >> 3) & 0x70);
}

// smem: 64B header (tmem ptr @0; done-mbar[s] @8+8s), then 1024-aligned data:
// 3 stages x 64KB (Ahi|Alo|Bhi|Blo 16KB each).
constexpr int TILE_B    = 16384;
constexpr int STAGE_B   = 4 * TILE_B;
constexpr int NSTAGE    = 3;
constexpr int SMEM_DYN  = 1024 + NSTAGE * STAGE_B + 1024;

// ---------------------------------------------------------------------------
// Batched GEMM: D[m,n] = sum_k A[m,k] * B[n,k]; A,B K-major in gmem.
// Tile 128x128, K-chunk 32.  BIASM: 0 none, 1 bias[n], 2 bias[m].
// CONV: B rows gathered from concat(Bg=mvT | Bc1=WLT | Bc2=ffT | Bc3=WRT).
// Mainloop: register double-buffered gmem loads (chunk ch+1 LDGs issued one
// full iteration before use) -> per-chunk critical path = STS + bar + issue;
// stage recycling via single tcgen05.commit arrival per stage (wait-only).
// ---------------------------------------------------------------------------
template<int BIASM, bool CONV>
__global__ void __launch_bounds__(256, 1)
tfgemm(const float* __restrict__ Ag, int lda, long long sA, int dA,
       const float* __restrict__ Bg, int ldb, long long sB, int dB,
       const float* __restrict__ Bc1, const float* __restrict__ Bc2,
       const float* __restrict__ Bc3,
       const float* __restrict__ bias,
       float* __restrict__ Cg, int ldc, long long sC, int K)
{
    extern __shared__ char smem[];
    const int tid  = threadIdx.x;
    const int z    = blockIdx.z;
    const int m0   = blockIdx.y * 128;
    const int n0   = blockIdx.x * 128;

    const uint32_t sbase = smem_u32(smem);
    const uint32_t data  = (sbase + 64 + 1023) & ~1023u;
    char* dptr = smem + (data - sbase);

    const float* A = Ag + (long long)(z / dA) * sA;
    const int nk = K >> 5;

    auto bsel = [&](int kc, const float*& bp, int& bld, int& bkc) {
        if (!CONV) {
            bp = Bg + (long long)(z / dB) * sB; bld = ldb; bkc = kc;
        } else {
            if      (kc < 512)  { bp = Bg  + (long long)z * ((long long)Pn * 512);        bld = 512; bkc = kc; }
            else if (kc < 1024) { bp = Bc1 + (long long)z * ((long long)Pn * 512);        bld = 512; bkc = kc - 512; }
            else if (kc < 1280) { bp = Bc2 + (long long)(z >> 2) * ((long long)Pn * 256); bld = 256; bkc = kc - 1024; }
            else                { bp = Bc3 + (long long)z * ((long long)Pn * 256);        bld = 256; bkc = kc - 1280; }
        }
    };

#if USE_TC
    // ======================= tcgen05 fast path (sm_103a) ====================
    const int wid  = tid >> 5;
    const int lane = tid & 31;
    const uint32_t hdr   = sbase;
    const uint32_t done0 = hdr + 8;     // 3 mbarriers, one per stage

    if (wid == 0) { TC_ALLOC(hdr, 128); TC_RELINQ(); }
    if (tid == 0) {
        #pragma unroll
        for (int s = 0; s < NSTAGE; ++s) MBAR_INIT(done0 + 8u * s, 1);
    }
    __syncthreads();
    uint32_t tmem;
    asm volatile("ld.shared.b32 %0, [%1];" : "=r"(tmem) : "r"(hdr));

    // chunk-invariant producer indexing: thread owns rows r0+32i, float4 col c4
    const int c4 = tid & 7;
    const int r0 = tid >> 3;
    uint32_t soff[4];
    #pragma unroll
    for (int i = 0; i < 4; ++i)
        soff[i] = sw128((uint32_t)((r0 + i * 32) * 128 + c4 * 16));
    const float* aptr = A + (size_t)(m0 + r0) * lda + c4 * 4;
    const size_t  astr = (size_t)32 * lda;
    const float* bptr0 = nullptr;
    size_t bstr = 0;
    if (!CONV) {
        bptr0 = Bg + (long long)(z / dB) * sB + (size_t)(n0 + r0) * ldb + c4 * 4;
        bstr  = (size_t)32 * ldb;
    }

    auto loadAB = [&](int ch, float4* va, float4* vb) {
        const int kc = ch << 5;
        #pragma unroll
        for (int i = 0; i < 4; ++i)
            va[i] = *reinterpret_cast<const float4*>(aptr + kc + (size_t)i * astr);
        if (!CONV) {
            #pragma unroll
            for (int i = 0; i < 4; ++i)
                vb[i] = *reinterpret_cast<const float4*>(bptr0 + kc + (size_t)i * bstr);
        } else {
            const float* bp; int bld, bkc;
            bsel(kc, bp, bld, bkc);
            const float* bt = bp + (size_t)(n0 + r0) * bld + bkc + c4 * 4;
            #pragma unroll
            for (int i = 0; i < 4; ++i)
                vb[i] = *reinterpret_cast<const float4*>(bt + (size_t)i * 32 * bld);
        }
    };

    // preload chunk 0
    float4 va[4], vb[4];
    loadAB(0, va, vb);

    for (int ch = 0; ch < nk; ++ch) {
        // prefetch chunk ch+1 a full iteration ahead (latency hidden by the
        // MMA/sync period of chunk ch)
        float4 na[4], nb[4];
        if (ch + 1 < nk) loadAB(ch + 1, na, nb);

        const int ps = ch % NSTAGE;
        const int rr = ch / NSTAGE;
        if (rr > 0) MBAR_WAIT(done0 + 8u * ps, (rr - 1) & 1);

        char* stg = dptr + ps * STAGE_B;
        #pragma unroll
        for (int i = 0; i < 4; ++i) {
            float4 hi, lo;
            split2(va[i].x, hi.x, lo.x); split2(va[i].y, hi.y, lo.y);
            split2(va[i].z, hi.z, lo.z); split2(va[i].w, hi.w, lo.w);
            *reinterpret_cast<float4*>(stg + soff[i])          = hi;
            *reinterpret_cast<float4*>(stg + TILE_B + soff[i]) = lo;
        }
        #pragma unroll
        for (int i = 0; i < 4; ++i) {
            float4 hi, lo;
            split2(vb[i].x, hi.x, lo.x); split2(vb[i].y, hi.y, lo.y);
            split2(vb[i].z, hi.z, lo.z); split2(vb[i].w, hi.w, lo.w);
            *reinterpret_cast<float4*>(stg + 2 * TILE_B + soff[i]) = hi;
            *reinterpret_cast<float4*>(stg + 3 * TILE_B + soff[i]) = lo;
        }

        __syncthreads();   // all producer stores for this stage are done

        if (tid == 0) {
            FENCE_ASYNC();
            uint32_t sb = data + ps * STAGE_B;
            uint64_t ah = sdesc(sb);
            uint64_t al = sdesc(sb + TILE_B);
            uint64_t bh = sdesc(sb + 2 * TILE_B);
            uint64_t bl = sdesc(sb + 3 * TILE_B);
            #pragma unroll
            for (int ks = 0; ks < 4; ++ks) {
                uint64_t o = (uint64_t)(ks * 2);
                mma_tf32(tmem, ah + o, bh + o, !(ch == 0 && ks == 0));
                mma_tf32(tmem, ah + o, bl + o, true);
                mma_tf32(tmem, al + o, bh + o, true);
            }
            TC_COMMIT(done0 + 8u * ps);
        }

        #pragma unroll
        for (int i = 0; i < 4; ++i) { va[i] = na[i]; vb[i] = nb[i]; }
    }

    // wait for the final commit (covers all prior MMAs)
    MBAR_WAIT(done0 + 8u * ((nk - 1) % NSTAGE), ((nk - 1) / NSTAGE) & 1);
    TC_FENCE_AFTER();

    // ---- epilogue: TMEM -> smem (padded) -> coalesced gmem ----
    float* sbuf = reinterpret_cast<float*>(dptr);  // 128 x 132 floats
    const int rsub = (wid & 3) * 32 + lane;
    const int g0   = (wid >> 2) * 2;

    #pragma unroll
    for (int gi = 0; gi < 2; ++gi) {
        const int g = g0 + gi;
        uint32_t r[32];
        TC_LD_X32(r, tmem + g * 32);
        TC_WAIT_LD();
        float rowb = (BIASM == 2) ? bias[m0 + rsub] : 0.0f;
        #pragma unroll
        for (int cc = 0; cc < 8; ++cc) {
            float4 v;
            v.x = __uint_as_float(r[cc * 4 + 0]);
            v.y = __uint_as_float(r[cc * 4 + 1]);
            v.z = __uint_as_float(r[cc * 4 + 2]);
            v.w = __uint_as_float(r[cc * 4 + 3]);
            if (BIASM == 1) {
                float4 bv = *reinterpret_cast<const float4*>(bias + n0 + g * 32 + cc * 4);
                v.x += bv.x; v.y += bv.y; v.z += bv.z; v.w += bv.w;
            } else if (BIASM == 2) {
                v.x += rowb; v.y += rowb; v.z += rowb; v.w += rowb;
            }
            *reinterpret_cast<float4*>(&sbuf[rsub * 132 + g * 32 + cc * 4]) = v;
        }
    }
    __syncthreads();

    float* C = Cg + (long long)z * sC;
    #pragma unroll
    for (int i = 0; i < 16; ++i) {
        int u   = tid + i * 256;
        int row = u >> 5, cc = u & 31;
        float4 v = *reinterpret_cast<const float4*>(&sbuf[row * 132 + cc * 4]);
        *reinterpret_cast<float4*>(C + (size_t)(m0 + row) * ldc + n0 + cc * 4) = v;
    }

    __syncthreads();
    if (wid == 0) TC_DEALLOC(tmem, 128);

#else
    // ================== portable FFMA fallback (plain sm_103) ===============
    float* As2 = reinterpret_cast<float*>(dptr);
    float* Bs2 = As2 + 32 * 128;

    const int tx = tid & 15, ty = tid >> 4;
    float acc[8][8];
    #pragma unroll
    for (int i = 0; i < 8; ++i)
        #pragma unroll
        for (int j = 0; j < 8; ++j) acc[i][j] = 0.0f;

    for (int ch = 0; ch < nk; ++ch) {
        const int kc = ch << 5;
        __syncthreads();
        #pragma unroll
        for (int i = 0; i < 4; ++i) {
            int u = tid + i * 256;
            int row = u >> 3, cc = u & 7;
            float4 v = *reinterpret_cast<const float4*>(
                A + (size_t)(m0 + row) * lda + kc + cc * 4);
            As2[(cc * 4 + 0) * 128 + row] = v.x;
            As2[(cc * 4 + 1) * 128 + row] = v.y;
            As2[(cc * 4 + 2) * 128 + row] = v.z;
            As2[(cc * 4 + 3) * 128 + row] = v.w;
        }
        const float* bp; int bld, bkc;
        bsel(kc, bp, bld, bkc);
        #pragma unroll
        for (int i = 0; i < 4; ++i) {
            int u = tid + i * 256;
            int row = u >> 3, cc = u & 7;
            float4 v = *reinterpret_cast<const float4*>(
                bp + (size_t)(n0 + row) * bld + bkc + cc * 4);
            Bs2[(cc * 4 + 0) * 128 + row] = v.x;
            Bs2[(cc * 4 + 1) * 128 + row] = v.y;
            Bs2[(cc * 4 + 2) * 128 + row] = v.z;
            Bs2[(cc * 4 + 3) * 128 + row] = v.w;
        }
        __syncthreads();
        #pragma unroll
        for (int kk = 0; kk < 32; ++kk) {
            float a[8], b[8];
            #pragma unroll
            for (int i = 0; i < 4; ++i) {
                a[i]     = As2[kk * 128 + ty * 4 + i];
                a[i + 4] = As2[kk * 128 + 64 + ty * 4 + i];
                b[i]     = Bs2[kk * 128 + tx * 4 + i];
                b[i + 4] = Bs2[kk * 128 + 64 + tx * 4 + i];
            }
            #pragma unroll
            for (int i = 0; i < 8; ++i)
                #pragma unroll
                for (int j = 0; j < 8; ++j)
                    acc[i][j] = fmaf(a[i], b[j], acc[i][j]);
        }
    }

    float* C = Cg + (long long)z * sC;
    #pragma unroll
    for (int i = 0; i < 8; ++i) {
        const int m = m0 + ((i < 4) ? (ty * 4 + i) : (64 + ty * 4 + i - 4));
        const float rowb = (BIASM == 2) ? bias[m] : 0.0f;
        #pragma unroll
        for (int jh = 0; jh < 2; ++jh) {
            const int n = n0 + jh * 64 + tx * 4;
            float4 v;
            v.x = acc[i][jh * 4 + 0]; v.y = acc[i][jh * 4 + 1];
            v.z = acc[i][jh * 4 + 2]; v.w = acc[i][jh * 4 + 3];
            if (BIASM == 1) {
                float4 bv = *reinterpret_cast<const float4*>(bias + n);
                v.x += bv.x; v.y += bv.y; v.z += bv.z; v.w += bv.w;
            } else if (BIASM == 2) {
                v.x += rowb; v.y += rowb; v.z += rowb; v.w += rowb;
            }
            *reinterpret_cast<float4*>(C + (size_t)m * ldc + n) = v;
        }
    }
#endif
}

// ---------------------------------------------------------------------------
// 32x32 tiled transpose: src [z][C][Pn] -> dst [z][Pn][C]
// ---------------------------------------------------------------------------
__global__ void __launch_bounds__(256)
transp(const float* __restrict__ src, float* __restrict__ dst, int C)
{
    __shared__ float tile[32][33];
    const int p0 = blockIdx.x * 32, c0 = blockIdx.y * 32;
    const float* s = src + (size_t)blockIdx.z * C * Pn;
    float*       d = dst + (size_t)blockIdx.z * C * Pn;
    #pragma unroll
    for (int j = 0; j < 32; j += 8)
        tile[threadIdx.y + j][threadIdx.x] =
            s[(size_t)(c0 + threadIdx.y + j) * Pn + p0 + threadIdx.x];
    __syncthreads();
    #pragma unroll
    for (int j = 0; j < 32; j += 8)
        d[(size_t)(p0 + threadIdx.y + j) * C + c0 + threadIdx.x] =
            tile[threadIdx.x][threadIdx.y + j];
}

// ---------------------------------------------------------------------------
// Row softmax over g_S: grid (Pn, BN_), 256 threads, 9 elems/thread in regs
// ---------------------------------------------------------------------------
__global__ __launch_bounds__(256)
void softmax_rows(float* __restrict__ S)
{
    const int tid = threadIdx.x;
    const size_t base = ((size_t)blockIdx.y * Pn + blockIdx.x) * Pn;

    float r[9];
    float mx = -3.4e38f;
    #pragma unroll
    for (int j = 0; j < 9; ++j) {
        r[j] = S[base + tid + j * 256];
        mx = fmaxf(mx, r[j]);
    }
    __shared__ float sred[8];
    #pragma unroll
    for (int o = 16; o > 0; o >>= 1)
        mx = fmaxf(mx, __shfl_xor_sync(0xffffffffu, mx, o));
    if ((tid & 31) == 0) sred[tid >> 5] = mx;
    __syncthreads();
    mx = sred[0];
    #pragma unroll
    for (int w = 1; w < 8; ++w) mx = fmaxf(mx, sred[w]);

    float s = 0.0f;
    #pragma unroll
    for (int j = 0; j < 9; ++j) { r[j] = __expf(r[j] - mx); s += r[j]; }
    #pragma unroll
    for (int o = 16; o > 0; o >>= 1)
        s += __shfl_xor_sync(0xffffffffu, s, o);
    __syncthreads();
    if ((tid & 31) == 0) sred[tid >> 5] = s;
    __syncthreads();
    s = 0.0f;
    #pragma unroll
    for (int w = 0; w < 8; ++w) s += sred[w];

    const float inv = 1.0f / s;
    #pragma unroll
    for (int j = 0; j < 9; ++j)
        S[base + tid + j * 256] = r[j] * inv;
}

// ---------------------------------------------------------------------------
// Launch sequence (default stream, graph-capturable)
// ---------------------------------------------------------------------------
extern "C" void kernel_launch(void* const* d_in, const int* in_sizes, int n_in,
                              void* d_out, int out_size)
{
    const float* mv  = (const float*)d_in[0];   // [16,512,P]
    const float* ff  = (const float*)d_in[1];   // [4,256,P]
    const float* wq1 = (const float*)d_in[2];
    const float* bq1 = (const float*)d_in[3];
    const float* wk1 = (const float*)d_in[4];
    const float* bk1 = (const float*)d_in[5];
    const float* wq2 = (const float*)d_in[6];
    const float* bq2 = (const float*)d_in[7];
    const float* wk2 = (const float*)d_in[8];
    const float* bk2 = (const float*)d_in[9];
    const float* wdr = (const float*)d_in[10];  // [512,1536]
    const float* bdr = (const float*)d_in[11];
    float* out = (float*)d_out;                 // [16,512,P]

    float *mvT, *ffT, *Q1t, *K1t, *Q2t, *K2t, *S, *WRT, *WLT;
    cudaGetSymbolAddress((void**)&mvT, g_mvT);
    cudaGetSymbolAddress((void**)&ffT, g_ffT);
    cudaGetSymbolAddress((void**)&Q1t, g_Q1t);
    cudaGetSymbolAddress((void**)&K1t, g_K1t);
    cudaGetSymbolAddress((void**)&Q2t, g_Q2t);
    cudaGetSymbolAddress((void**)&K2t, g_K2t);
    cudaGetSymbolAddress((void**)&S,   g_S);
    cudaGetSymbolAddress((void**)&WRT, g_WRT);
    cudaGetSymbolAddress((void**)&WLT, g_WLT);

    cudaFuncSetAttribute(tfgemm<0, false>, cudaFuncAttributeMaxDynamicSharedMemorySize, SMEM_DYN);
    cudaFuncSetAttribute(tfgemm<1, false>, cudaFuncAttributeMaxDynamicSharedMemorySize, SMEM_DYN);
    cudaFuncSetAttribute(tfgemm<2, true>,  cudaFuncAttributeMaxDynamicSharedMemorySize, SMEM_DYN);

    const long long sMVT = (long long)Pn * CX_;
    const long long sFFT = (long long)Pn * CF_;
    const long long sHT  = (long long)Pn * HID_;
    const long long sS   = (long long)Pn * Pn;
    const long long sWRT = (long long)Pn * CF_;
    const long long sWLT = (long long)Pn * CX_;
    const long long sO   = (long long)OUT_ * Pn;

    // transposes -> K-major inputs
    transp<<<dim3(Pn / 32, CX_ / 32, 16), dim3(32, 8)>>>(mv, mvT, CX_);
    transp<<<dim3(Pn / 32, CF_ / 32, 4),  dim3(32, 8)>>>(ff, ffT, CF_);

    // projections: D[p,h] = sum_c X[p,c] * W[h,c] + b[h]
    tfgemm<1, false><<<dim3(2, 18, 16), 256, SMEM_DYN>>>(
        mvT, CX_, sMVT, 1,  wq1, CX_, 0LL, 1,  nullptr, nullptr, nullptr,
        bq1,  Q1t, HID_, sHT, CX_);
    tfgemm<1, false><<<dim3(2, 18, 4), 256, SMEM_DYN>>>(
        ffT, CF_, sFFT, 1,  wk1, CF_, 0LL, 1,  nullptr, nullptr, nullptr,
        bk1,  K1t, HID_, sHT, CF_);
    tfgemm<1, false><<<dim3(2, 18, 4), 256, SMEM_DYN>>>(
        ffT, CF_, sFFT, 1,  wq2, CF_, 0LL, 1,  nullptr, nullptr, nullptr,
        bq2,  Q2t, HID_, sHT, CF_);
    tfgemm<1, false><<<dim3(2, 18, 16), 256, SMEM_DYN>>>(
        mvT, CX_, sMVT, 1,  wk2, CX_, 0LL, 1,  nullptr, nullptr, nullptr,
        bk2,  K2t, HID_, sHT, CX_);

    // layer 1: S[p,q] = Q1t[p,:].K1t[q,:]; softmax; WRT[p,c] = S[p,:].ff[c,:]
    tfgemm<0, false><<<dim3(18, 18, 16), 256, SMEM_DYN>>>(
        Q1t, HID_, sHT, 1,  K1t, HID_, sHT, 4,  nullptr, nullptr, nullptr,
        nullptr,  S, Pn, sS, HID_);
    softmax_rows<<<dim3(Pn, BN_), 256>>>(S);
    tfgemm<0, false><<<dim3(2, 18, 16), 256, SMEM_DYN>>>(
        S, Pn, sS, 1,  ff, Pn, (long long)CF_ * Pn, 4,  nullptr, nullptr, nullptr,
        nullptr,  WRT, CF_, sWRT, Pn);

    // layer 2
    tfgemm<0, false><<<dim3(18, 18, 16), 256, SMEM_DYN>>>(
        Q2t, HID_, sHT, 4,  K2t, HID_, sHT, 1,  nullptr, nullptr, nullptr,
        nullptr,  S, Pn, sS, HID_);
    softmax_rows<<<dim3(Pn, BN_), 256>>>(S);
    tfgemm<0, false><<<dim3(4, 18, 16), 256, SMEM_DYN>>>(
        S, Pn, sS, 1,  mv, Pn, (long long)CX_ * Pn, 1,  nullptr, nullptr, nullptr,
        nullptr,  WLT, CX_, sWLT, Pn);

    // fused conv: out[o,p] = sum_f wdr[o,f] * featT[p,f] + bdr[o], K=1536
    tfgemm<2, true><<<dim3(18, 4, 16), 256, SMEM_DYN>>>(
        wdr, 1536, 0LL, 1,  mvT, 0, 0LL, 1,  WLT, ffT, WRT,
        bdr,  out, Pn, sO, 1536);
}

// round 15
// speedup vs baseline: 1.3454x; 1.0428x over previous
#include <cuda_runtime.h>
#include <cstdint>

// ---------------------------------------------------------------------------
// Arch gate: tcgen05 only exists on the arch-specific (sm_103a) target. The
// harness also compiles a plain compute_103 target, which must fall back.
// ---------------------------------------------------------------------------
#if defined(__CUDA_ARCH_FEAT_SM103_ALL) || defined(__CUDA_ARCH_FEAT_SM100_ALL) || \
    defined(__CUDA_ARCH_SPECIFIC__) || defined(__CUDA_ARCH_FAMILY_SPECIFIC__)
#define USE_TC 1
#else
#define USE_TC 0
#endif

// ---------------------------------------------------------------------------
// Problem constants
// ---------------------------------------------------------------------------
constexpr int Pn   = 48 * 48;   // 2304
constexpr int CX_  = 512;
constexpr int CF_  = 256;
constexpr int HID_ = 256;
constexpr int OUT_ = 512;
constexpr int BN_  = 16;

// ---------------------------------------------------------------------------
// Scratch (device globals; no allocation allowed). Everything K-major for its
// consumer GEMM.
// ---------------------------------------------------------------------------
__device__ float g_mvT[(size_t)BN_ * Pn * CX_];   // [z][p][cx]
__device__ float g_ffT[(size_t)4   * Pn * CF_];   // [b][p][cf]
__device__ float g_Q1t[(size_t)BN_ * Pn * HID_];  // [z][p][h]
__device__ float g_K1t[(size_t)4   * Pn * HID_];
__device__ float g_Q2t[(size_t)4   * Pn * HID_];
__device__ float g_K2t[(size_t)BN_ * Pn * HID_];
__device__ float g_S  [(size_t)BN_ * Pn * Pn];    // scores/attn (both layers)
__device__ float g_WRT[(size_t)BN_ * Pn * CF_];   // [z][p][cf]
__device__ float g_WLT[(size_t)BN_ * Pn * CX_];   // [z][p][cx]

// ---------------------------------------------------------------------------
// PTX helpers
// ---------------------------------------------------------------------------
__device__ __forceinline__ uint32_t smem_u32(const void* p) {
    uint32_t a;
    asm("{ .reg .u64 t; cvta.to.shared.u64 t, %1; cvt.u32.u64 %0, t; }"
        : "=r"(a) : "l"(p));
    return a;
}
// Bitmask hi/lo split: hi keeps the top 10 mantissa bits (tf32-exact), lo is
// the exact residual; lo's own tf32 truncation leaves ~2^-23 relative error.
__device__ __forceinline__ void split2(float x, float& hi, float& lo) {
    hi = __uint_as_float(__float_as_uint(x) & 0xffffe000u);
    lo = x - hi;
}

#define MBAR_INIT(a, c) \
    asm volatile("mbarrier.init.shared.b64 [%0], %1;" :: "r"(a), "r"(c) : "memory")
#define MBAR_ARRIVE(a) \
    asm volatile("mbarrier.arrive.shared.b64 _, [%0];" :: "r"(a) : "memory")
#define MBAR_WAIT(a, ph) do {                                                  \
    uint32_t _m = (a), _p = (ph), _d = 0;                                      \
    while (!_d) {                                                              \
        asm volatile("{\n\t.reg .pred p;\n\t"                                  \
            "mbarrier.try_wait.parity.acquire.cta.shared::cta.b64 p, [%1], %2, 0x989680;\n\t" \
            "selp.b32 %0, 1, 0, p;\n\t}"                                       \
            : "=r"(_d) : "r"(_m), "r"(_p) : "memory");                         \
    } } while (0)

#define TC_ALLOC(sa, nc) \
    asm volatile("tcgen05.alloc.cta_group::1.sync.aligned.shared::cta.b32 [%0], %1;" \
        :: "r"(sa), "r"((uint32_t)(nc)) : "memory")
#define TC_RELINQ() \
    asm volatile("tcgen05.relinquish_alloc_permit.cta_group::1.sync.aligned;")
#define TC_DEALLOC(tm, nc) \
    asm volatile("tcgen05.dealloc.cta_group::1.sync.aligned.b32 %0, %1;" \
        :: "r"(tm), "r"((uint32_t)(nc)))
#define TC_COMMIT(mb) \
    asm volatile("tcgen05.commit.cta_group::1.mbarrier::arrive::one.shared::cluster.b64 [%0];" \
        :: "r"(mb) : "memory")
#define TC_FENCE_AFTER() asm volatile("tcgen05.fence::after_thread_sync;" ::: "memory")
#define TC_WAIT_LD()     asm volatile("tcgen05.wait::ld.sync.aligned;" ::: "memory")
#define FENCE_ASYNC()    asm volatile("fence.proxy.async.shared::cta;" ::: "memory")

#define TC_LD_X32(r, ta) \
    asm volatile("tcgen05.ld.sync.aligned.32x32b.x32.b32 " \
        "{%0,%1,%2,%3,%4,%5,%6,%7,%8,%9,%10,%11,%12,%13,%14,%15," \
        "%16,%17,%18,%19,%20,%21,%22,%23,%24,%25,%26,%27,%28,%29,%30,%31}, [%32];" \
        : "=r"((r)[0]),"=r"((r)[1]),"=r"((r)[2]),"=r"((r)[3]),   \
          "=r"((r)[4]),"=r"((r)[5]),"=r"((r)[6]),"=r"((r)[7]),   \
          "=r"((r)[8]),"=r"((r)[9]),"=r"((r)[10]),"=r"((r)[11]), \
          "=r"((r)[12]),"=r"((r)[13]),"=r"((r)[14]),"=r"((r)[15]),\
          "=r"((r)[16]),"=r"((r)[17]),"=r"((r)[18]),"=r"((r)[19]),\
          "=r"((r)[20]),"=r"((r)[21]),"=r"((r)[22]),"=r"((r)[23]),\
          "=r"((r)[24]),"=r"((r)[25]),"=r"((r)[26]),"=r"((r)[27]),\
          "=r"((r)[28]),"=r"((r)[29]),"=r"((r)[30]),"=r"((r)[31]) \
        : "r"(ta))

// idesc: D=F32(1<<4), A=TF32(2<<7), B=TF32(2<<10), N=128 (N/8 @17), M=128 (M/16 @24)
constexpr uint32_t IDESC_TF32 =
    (1u << 4) | (2u << 7) | (2u << 10) | ((128u / 8) << 17) | ((128u / 16) << 24);

__device__ __forceinline__ void mma_tf32(uint32_t d, uint64_t ad, uint64_t bd, bool acc) {
    asm volatile("{\n\t.reg .pred p;\n\tsetp.ne.u32 p, %5, 0;\n\t"
        "tcgen05.mma.cta_group::1.kind::tf32 [%0], %1, %2, %3, {%4,%4,%4,%4}, p;\n\t}"
        :: "r"(d), "l"(ad), "l"(bd), "r"(IDESC_TF32), "r"(0u), "r"(acc ? 1u : 0u)
        : "memory");
}

// SW128 K-major smem descriptor: layout=2, version=1, SBO=64, LBO=1
constexpr uint64_t DESC_BASE =
    (2ull << 61) | (1ull << 46) | (64ull << 32) | (1ull << 16);
__device__ __forceinline__ uint64_t sdesc(uint32_t addr) {
    return DESC_BASE | ((uint64_t)(addr >> 4) & 0x3FFFull);
}
__device__ __forceinline__ uint32_t sw128(uint32_t off) {
    return off ^ ((off >> 3) & 0x70);
}

// smem: 64B header (tmem ptr @0; full-mbar[s] @8+8s; free-mbar[s] @32+8s),
// then 1024-aligned data: 3 stages x 64KB (Ahi|Alo|Bhi|Blo 16KB each).
constexpr int TILE_B    = 16384;
constexpr int STAGE_B   = 4 * TILE_B;
constexpr int NSTAGE    = 3;
constexpr int SMEM_DYN  = 1024 + NSTAGE * STAGE_B + 1024;
constexpr int NTHREADS  = 288;   // 8 producer warps + 1 MMA warp

// ---------------------------------------------------------------------------
// Batched GEMM: D[m,n] = sum_k A[m,k] * B[n,k]; A,B K-major in gmem.
// Tile 128x128, K-chunk 32.  BIASM: 0 none, 1 bias[n], 2 bias[m].
// CONV: B rows gathered from concat(Bg=mvT | Bc1=WLT | Bc2=ffT | Bc3=WRT).
// Warp-specialized: warps 0-7 produce (reg-double-buffered LDG -> split ->
// STS -> 1 elected arrive/warp on full[ps]); warp 8 lane 0 issues MMAs
// (wait full -> fence -> 12 dispatches -> commit(free[ps])). No per-chunk
// __syncthreads -- producer and tensor pipelines run decoupled.
// ---------------------------------------------------------------------------
template<int BIASM, bool CONV>
__global__ void __launch_bounds__(NTHREADS, 1)
tfgemm(const float* __restrict__ Ag, int lda, long long sA, int dA,
       const float* __restrict__ Bg, int ldb, long long sB, int dB,
       const float* __restrict__ Bc1, const float* __restrict__ Bc2,
       const float* __restrict__ Bc3,
       const float* __restrict__ bias,
       float* __restrict__ Cg, int ldc, long long sC, int K)
{
    extern __shared__ char smem[];
    const int tid  = threadIdx.x;
    const int z    = blockIdx.z;
    const int m0   = blockIdx.y * 128;
    const int n0   = blockIdx.x * 128;

    const uint32_t sbase = smem_u32(smem);
    const uint32_t data  = (sbase + 64 + 1023) & ~1023u;
    char* dptr = smem + (data - sbase);

    const float* A = Ag + (long long)(z / dA) * sA;
    const int nk = K >> 5;

    auto bsel = [&](int kc, const float*& bp, int& bld, int& bkc) {
        if (!CONV) {
            bp = Bg + (long long)(z / dB) * sB; bld = ldb; bkc = kc;
        } else {
            if      (kc < 512)  { bp = Bg  + (long long)z * ((long long)Pn * 512);        bld = 512; bkc = kc; }
            else if (kc < 1024) { bp = Bc1 + (long long)z * ((long long)Pn * 512);        bld = 512; bkc = kc - 512; }
            else if (kc < 1280) { bp = Bc2 + (long long)(z >> 2) * ((long long)Pn * 256); bld = 256; bkc = kc - 1024; }
            else                { bp = Bc3 + (long long)z * ((long long)Pn * 256);        bld = 256; bkc = kc - 1280; }
        }
    };

#if USE_TC
    // ======================= tcgen05 fast path (sm_103a) ====================
    const int wid  = tid >> 5;
    const int lane = tid & 31;
    const uint32_t hdr   = sbase;
    const uint32_t full0 = hdr + 8;     // 3 mbarriers, 8 arrivals each
    const uint32_t free0 = hdr + 32;    // 3 mbarriers, 1 arrival (commit)

    if (wid == 8) { TC_ALLOC(hdr, 128); TC_RELINQ(); }
    if (tid == 0) {
        #pragma unroll
        for (int s = 0; s < NSTAGE; ++s) {
            MBAR_INIT(full0 + 8u * s, 8);
            MBAR_INIT(free0 + 8u * s, 1);
        }
    }
    __syncthreads();
    uint32_t tmem;
    asm volatile("ld.shared.b32 %0, [%1];" : "=r"(tmem) : "r"(hdr));

    if (wid < 8) {
        // ---------------- producer warps (threads 0..255) ------------------
        const int c4 = tid & 7;
        const int r0 = tid >> 3;
        uint32_t soff[4];
        #pragma unroll
        for (int i = 0; i < 4; ++i)
            soff[i] = sw128((uint32_t)((r0 + i * 32) * 128 + c4 * 16));
        const float* aptr = A + (size_t)(m0 + r0) * lda + c4 * 4;
        const size_t  astr = (size_t)32 * lda;
        const float* bptr0 = nullptr;
        size_t bstr = 0;
        if (!CONV) {
            bptr0 = Bg + (long long)(z / dB) * sB + (size_t)(n0 + r0) * ldb + c4 * 4;
            bstr  = (size_t)32 * ldb;
        }

        auto loadAB = [&](int ch, float4* va, float4* vb) {
            const int kc = ch << 5;
            #pragma unroll
            for (int i = 0; i < 4; ++i)
                va[i] = *reinterpret_cast<const float4*>(aptr + kc + (size_t)i * astr);
            if (!CONV) {
                #pragma unroll
                for (int i = 0; i < 4; ++i)
                    vb[i] = *reinterpret_cast<const float4*>(bptr0 + kc + (size_t)i * bstr);
            } else {
                const float* bp; int bld, bkc;
                bsel(kc, bp, bld, bkc);
                const float* bt = bp + (size_t)(n0 + r0) * bld + bkc + c4 * 4;
                #pragma unroll
                for (int i = 0; i < 4; ++i)
                    vb[i] = *reinterpret_cast<const float4*>(bt + (size_t)i * 32 * bld);
            }
        };

        float4 va[4], vb[4];
        loadAB(0, va, vb);

        for (int ch = 0; ch < nk; ++ch) {
            float4 na[4], nb[4];
            if (ch + 1 < nk) loadAB(ch + 1, na, nb);   // prefetch 1 iter ahead

            const int ps = ch % NSTAGE;
            const int rr = ch / NSTAGE;
            if (rr > 0) MBAR_WAIT(free0 + 8u * ps, (rr - 1) & 1);

            char* stg = dptr + ps * STAGE_B;
            #pragma unroll
            for (int i = 0; i < 4; ++i) {
                float4 hi, lo;
                split2(va[i].x, hi.x, lo.x); split2(va[i].y, hi.y, lo.y);
                split2(va[i].z, hi.z, lo.z); split2(va[i].w, hi.w, lo.w);
                *reinterpret_cast<float4*>(stg + soff[i])          = hi;
                *reinterpret_cast<float4*>(stg + TILE_B + soff[i]) = lo;
            }
            #pragma unroll
            for (int i = 0; i < 4; ++i) {
                float4 hi, lo;
                split2(vb[i].x, hi.x, lo.x); split2(vb[i].y, hi.y, lo.y);
                split2(vb[i].z, hi.z, lo.z); split2(vb[i].w, hi.w, lo.w);
                *reinterpret_cast<float4*>(stg + 2 * TILE_B + soff[i]) = hi;
                *reinterpret_cast<float4*>(stg + 3 * TILE_B + soff[i]) = lo;
            }

            __syncwarp();
            if (lane == 0) MBAR_ARRIVE(full0 + 8u * ps);

            #pragma unroll
            for (int i = 0; i < 4; ++i) { va[i] = na[i]; vb[i] = nb[i]; }
        }
    } else if (lane == 0) {
        // ---------------- MMA issuer (warp 8, lane 0) ----------------------
        for (int ch = 0; ch < nk; ++ch) {
            const int ps = ch % NSTAGE;
            const int rr = ch / NSTAGE;
            MBAR_WAIT(full0 + 8u * ps, rr & 1);
            FENCE_ASYNC();
            uint32_t sb = data + ps * STAGE_B;
            uint64_t ah = sdesc(sb);
            uint64_t al = sdesc(sb + TILE_B);
            uint64_t bh = sdesc(sb + 2 * TILE_B);
            uint64_t bl = sdesc(sb + 3 * TILE_B);
            #pragma unroll
            for (int ks = 0; ks < 4; ++ks) {
                uint64_t o = (uint64_t)(ks * 2);
                mma_tf32(tmem, ah + o, bh + o, !(ch == 0 && ks == 0));
                mma_tf32(tmem, ah + o, bl + o, true);
                mma_tf32(tmem, al + o, bh + o, true);
            }
            TC_COMMIT(free0 + 8u * ps);
        }
    }

    // ---- epilogue (warps 0-7): wait final commit, TMEM -> smem -> gmem ----
    if (wid < 8) {
        MBAR_WAIT(free0 + 8u * ((nk - 1) % NSTAGE), ((nk - 1) / NSTAGE) & 1);
        TC_FENCE_AFTER();

        float* sbuf = reinterpret_cast<float*>(dptr);  // 128 x 132 floats
        const int rsub = (wid & 3) * 32 + lane;
        const int g0   = (wid >> 2) * 2;

        #pragma unroll
        for (int gi = 0; gi < 2; ++gi) {
            const int g = g0 + gi;
            uint32_t r[32];
            TC_LD_X32(r, tmem + g * 32);
            TC_WAIT_LD();
            float rowb = (BIASM == 2) ? bias[m0 + rsub] : 0.0f;
            #pragma unroll
            for (int cc = 0; cc < 8; ++cc) {
                float4 v;
                v.x = __uint_as_float(r[cc * 4 + 0]);
                v.y = __uint_as_float(r[cc * 4 + 1]);
                v.z = __uint_as_float(r[cc * 4 + 2]);
                v.w = __uint_as_float(r[cc * 4 + 3]);
                if (BIASM == 1) {
                    float4 bv = *reinterpret_cast<const float4*>(bias + n0 + g * 32 + cc * 4);
                    v.x += bv.x; v.y += bv.y; v.z += bv.z; v.w += bv.w;
                } else if (BIASM == 2) {
                    v.x += rowb; v.y += rowb; v.z += rowb; v.w += rowb;
                }
                *reinterpret_cast<float4*>(&sbuf[rsub * 132 + g * 32 + cc * 4]) = v;
            }
        }
    }
    __syncthreads();

    if (wid < 8) {
        float* sbuf = reinterpret_cast<float*>(dptr);
        float* C = Cg + (long long)z * sC;
        #pragma unroll
        for (int i = 0; i < 16; ++i) {
            int u   = tid + i * 256;
            int row = u >> 5, cc = u & 31;
            float4 v = *reinterpret_cast<const float4*>(&sbuf[row * 132 + cc * 4]);
            *reinterpret_cast<float4*>(C + (size_t)(m0 + row) * ldc + n0 + cc * 4) = v;
        }
    }

    __syncthreads();
    if (wid == 8) TC_DEALLOC(tmem, 128);

#else
    // ================== portable FFMA fallback (plain sm_103) ===============
    float* As2 = reinterpret_cast<float*>(dptr);
    float* Bs2 = As2 + 32 * 128;

    const int tx = tid & 15, ty = tid >> 4;
    float acc[8][8];
    #pragma unroll
    for (int i = 0; i < 8; ++i)
        #pragma unroll
        for (int j = 0; j < 8; ++j) acc[i][j] = 0.0f;

    for (int ch = 0; ch < nk; ++ch) {
        const int kc = ch << 5;
        __syncthreads();
        if (tid < 256) {
            #pragma unroll
            for (int i = 0; i < 4; ++i) {
                int u = tid + i * 256;
                int row = u >> 3, cc = u & 7;
                float4 v = *reinterpret_cast<const float4*>(
                    A + (size_t)(m0 + row) * lda + kc + cc * 4);
                As2[(cc * 4 + 0) * 128 + row] = v.x;
                As2[(cc * 4 + 1) * 128 + row] = v.y;
                As2[(cc * 4 + 2) * 128 + row] = v.z;
                As2[(cc * 4 + 3) * 128 + row] = v.w;
            }
            const float* bp; int bld, bkc;
            bsel(kc, bp, bld, bkc);
            #pragma unroll
            for (int i = 0; i < 4; ++i) {
                int u = tid + i * 256;
                int row = u >> 3, cc = u & 7;
                float4 v = *reinterpret_cast<const float4*>(
                    bp + (size_t)(n0 + row) * bld + bkc + cc * 4);
                Bs2[(cc * 4 + 0) * 128 + row] = v.x;
                Bs2[(cc * 4 + 1) * 128 + row] = v.y;
                Bs2[(cc * 4 + 2) * 128 + row] = v.z;
                Bs2[(cc * 4 + 3) * 128 + row] = v.w;
            }
        }
        __syncthreads();
        if (tid < 256) {
            #pragma unroll
            for (int kk = 0; kk < 32; ++kk) {
                float a[8], b[8];
                #pragma unroll
                for (int i = 0; i < 4; ++i) {
                    a[i]     = As2[kk * 128 + ty * 4 + i];
                    a[i + 4] = As2[kk * 128 + 64 + ty * 4 + i];
                    b[i]     = Bs2[kk * 128 + tx * 4 + i];
                    b[i + 4] = Bs2[kk * 128 + 64 + tx * 4 + i];
                }
                #pragma unroll
                for (int i = 0; i < 8; ++i)
                    #pragma unroll
                    for (int j = 0; j < 8; ++j)
                        acc[i][j] = fmaf(a[i], b[j], acc[i][j]);
            }
        }
    }

    if (tid < 256) {
        float* C = Cg + (long long)z * sC;
        #pragma unroll
        for (int i = 0; i < 8; ++i) {
            const int m = m0 + ((i < 4) ? (ty * 4 + i) : (64 + ty * 4 + i - 4));
            const float rowb = (BIASM == 2) ? bias[m] : 0.0f;
            #pragma unroll
            for (int jh = 0; jh < 2; ++jh) {
                const int n = n0 + jh * 64 + tx * 4;
                float4 v;
                v.x = acc[i][jh * 4 + 0]; v.y = acc[i][jh * 4 + 1];
                v.z = acc[i][jh * 4 + 2]; v.w = acc[i][jh * 4 + 3];
                if (BIASM == 1) {
                    float4 bv = *reinterpret_cast<const float4*>(bias + n);
                    v.x += bv.x; v.y += bv.y; v.z += bv.z; v.w += bv.w;
                } else if (BIASM == 2) {
                    v.x += rowb; v.y += rowb; v.z += rowb; v.w += rowb;
                }
                *reinterpret_cast<float4*>(C + (size_t)m * ldc + n) = v;
            }
        }
    }
#endif
}

// ---------------------------------------------------------------------------
// 32x32 tiled transpose: src [z][C][Pn] -> dst [z][Pn][C]
// ---------------------------------------------------------------------------
__global__ void __launch_bounds__(256)
transp(const float* __restrict__ src, float* __restrict__ dst, int C)
{
    __shared__ float tile[32][33];
    const int p0 = blockIdx.x * 32, c0 = blockIdx.y * 32;
    const float* s = src + (size_t)blockIdx.z * C * Pn;
    float*       d = dst + (size_t)blockIdx.z * C * Pn;
    #pragma unroll
    for (int j = 0; j < 32; j += 8)
        tile[threadIdx.y + j][threadIdx.x] =
            s[(size_t)(c0 + threadIdx.y + j) * Pn + p0 + threadIdx.x];
    __syncthreads();
    #pragma unroll
    for (int j = 0; j < 32; j += 8)
        d[(size_t)(p0 + threadIdx.y + j) * C + c0 + threadIdx.x] =
            tile[threadIdx.x][threadIdx.y + j];
}

// ---------------------------------------------------------------------------
// Row softmax over g_S: grid (Pn, BN_), 256 threads, 9 elems/thread in regs
// ---------------------------------------------------------------------------
__global__ __launch_bounds__(256)
void softmax_rows(float* __restrict__ S)
{
    const int tid = threadIdx.x;
    const size_t base = ((size_t)blockIdx.y * Pn + blockIdx.x) * Pn;

    float r[9];
    float mx = -3.4e38f;
    #pragma unroll
    for (int j = 0; j < 9; ++j) {
        r[j] = S[base + tid + j * 256];
        mx = fmaxf(mx, r[j]);
    }
    __shared__ float sred[8];
    #pragma unroll
    for (int o = 16; o > 0; o >>= 1)
        mx = fmaxf(mx, __shfl_xor_sync(0xffffffffu, mx, o));
    if ((tid & 31) == 0) sred[tid >> 5] = mx;
    __syncthreads();
    mx = sred[0];
    #pragma unroll
    for (int w = 1; w < 8; ++w) mx = fmaxf(mx, sred[w]);

    float s = 0.0f;
    #pragma unroll
    for (int j = 0; j < 9; ++j) { r[j] = __expf(r[j] - mx); s += r[j]; }
    #pragma unroll
    for (int o = 16; o > 0; o >>= 1)
        s += __shfl_xor_sync(0xffffffffu, s, o);
    __syncthreads();
    if ((tid & 31) == 0) sred[tid >> 5] = s;
    __syncthreads();
    s = 0.0f;
    #pragma unroll
    for (int w = 0; w < 8; ++w) s += sred[w];

    const float inv = 1.0f / s;
    #pragma unroll
    for (int j = 0; j < 9; ++j)
        S[base + tid + j * 256] = r[j] * inv;
}

// ---------------------------------------------------------------------------
// Launch sequence (default stream, graph-capturable)
// ---------------------------------------------------------------------------
extern "C" void kernel_launch(void* const* d_in, const int* in_sizes, int n_in,
                              void* d_out, int out_size)
{
    const float* mv  = (const float*)d_in[0];   // [16,512,P]
    const float* ff  = (const float*)d_in[1];   // [4,256,P]
    const float* wq1 = (const float*)d_in[2];
    const float* bq1 = (const float*)d_in[3];
    const float* wk1 = (const float*)d_in[4];
    const float* bk1 = (const float*)d_in[5];
    const float* wq2 = (const float*)d_in[6];
    const float* bq2 = (const float*)d_in[7];
    const float* wk2 = (const float*)d_in[8];
    const float* bk2 = (const float*)d_in[9];
    const float* wdr = (const float*)d_in[10];  // [512,1536]
    const float* bdr = (const float*)d_in[11];
    float* out = (float*)d_out;                 // [16,512,P]

    float *mvT, *ffT, *Q1t, *K1t, *Q2t, *K2t, *S, *WRT, *WLT;
    cudaGetSymbolAddress((void**)&mvT, g_mvT);
    cudaGetSymbolAddress((void**)&ffT, g_ffT);
    cudaGetSymbolAddress((void**)&Q1t, g_Q1t);
    cudaGetSymbolAddress((void**)&K1t, g_K1t);
    cudaGetSymbolAddress((void**)&Q2t, g_Q2t);
    cudaGetSymbolAddress((void**)&K2t, g_K2t);
    cudaGetSymbolAddress((void**)&S,   g_S);
    cudaGetSymbolAddress((void**)&WRT, g_WRT);
    cudaGetSymbolAddress((void**)&WLT, g_WLT);

    cudaFuncSetAttribute(tfgemm<0, false>, cudaFuncAttributeMaxDynamicSharedMemorySize, SMEM_DYN);
    cudaFuncSetAttribute(tfgemm<1, false>, cudaFuncAttributeMaxDynamicSharedMemorySize, SMEM_DYN);
    cudaFuncSetAttribute(tfgemm<2, true>,  cudaFuncAttributeMaxDynamicSharedMemorySize, SMEM_DYN);

    const long long sMVT = (long long)Pn * CX_;
    const long long sFFT = (long long)Pn * CF_;
    const long long sHT  = (long long)Pn * HID_;
    const long long sS   = (long long)Pn * Pn;
    const long long sWRT = (long long)Pn * CF_;
    const long long sWLT = (long long)Pn * CX_;
    const long long sO   = (long long)OUT_ * Pn;

    // transposes -> K-major inputs
    transp<<<dim3(Pn / 32, CX_ / 32, 16), dim3(32, 8)>>>(mv, mvT, CX_);
    transp<<<dim3(Pn / 32, CF_ / 32, 4),  dim3(32, 8)>>>(ff, ffT, CF_);

    // projections: D[p,h] = sum_c X[p,c] * W[h,c] + b[h]
    tfgemm<1, false><<<dim3(2, 18, 16), NTHREADS, SMEM_DYN>>>(
        mvT, CX_, sMVT, 1,  wq1, CX_, 0LL, 1,  nullptr, nullptr, nullptr,
        bq1,  Q1t, HID_, sHT, CX_);
    tfgemm<1, false><<<dim3(2, 18, 4), NTHREADS, SMEM_DYN>>>(
        ffT, CF_, sFFT, 1,  wk1, CF_, 0LL, 1,  nullptr, nullptr, nullptr,
        bk1,  K1t, HID_, sHT, CF_);
    tfgemm<1, false><<<dim3(2, 18, 4), NTHREADS, SMEM_DYN>>>(
        ffT, CF_, sFFT, 1,  wq2, CF_, 0LL, 1,  nullptr, nullptr, nullptr,
        bq2,  Q2t, HID_, sHT, CF_);
    tfgemm<1, false><<<dim3(2, 18, 16), NTHREADS, SMEM_DYN>>>(
        mvT, CX_, sMVT, 1,  wk2, CX_, 0LL, 1,  nullptr, nullptr, nullptr,
        bk2,  K2t, HID_, sHT, CX_);

    // layer 1: S[p,q] = Q1t[p,:].K1t[q,:]; softmax; WRT[p,c] = S[p,:].ff[c,:]
    tfgemm<0, false><<<dim3(18, 18, 16), NTHREADS, SMEM_DYN>>>(
        Q1t, HID_, sHT, 1,  K1t, HID_, sHT, 4,  nullptr, nullptr, nullptr,
        nullptr,  S, Pn, sS, HID_);
    softmax_rows<<<dim3(Pn, BN_), 256>>>(S);
    tfgemm<0, false><<<dim3(2, 18, 16), NTHREADS, SMEM_DYN>>>(
        S, Pn, sS, 1,  ff, Pn, (long long)CF_ * Pn, 4,  nullptr, nullptr, nullptr,
        nullptr,  WRT, CF_, sWRT, Pn);

    // layer 2
    tfgemm<0, false><<<dim3(18, 18, 16), NTHREADS, SMEM_DYN>>>(
        Q2t, HID_, sHT, 4,  K2t, HID_, sHT, 1,  nullptr, nullptr, nullptr,
        nullptr,  S, Pn, sS, HID_);
    softmax_rows<<<dim3(Pn, BN_), 256>>>(S);
    tfgemm<0, false><<<dim3(4, 18, 16), NTHREADS, SMEM_DYN>>>(
        S, Pn, sS, 1,  mv, Pn, (long long)CX_ * Pn, 1,  nullptr, nullptr, nullptr,
        nullptr,  WLT, CX_, sWLT, Pn);

    // fused conv: out[o,p] = sum_f wdr[o,f] * featT[p,f] + bdr[o], K=1536
    tfgemm<2, true><<<dim3(18, 4, 16), NTHREADS, SMEM_DYN>>>(
        wdr, 1536, 0LL, 1,  mvT, 0, 0LL, 1,  WLT, ffT, WRT,
        bdr,  out, Pn, sO, 1536);
}

// round 16
// speedup vs baseline: 1.4649x; 1.0889x over previous
#include <cuda_runtime.h>
#include <cstdint>

// ---------------------------------------------------------------------------
// Arch gate: tcgen05 only exists on the arch-specific (sm_103a) target. The
// harness also compiles a plain compute_103 target, which must fall back.
// ---------------------------------------------------------------------------
#if defined(__CUDA_ARCH_FEAT_SM103_ALL) || defined(__CUDA_ARCH_FEAT_SM100_ALL) || \
    defined(__CUDA_ARCH_SPECIFIC__) || defined(__CUDA_ARCH_FAMILY_SPECIFIC__)
#define USE_TC 1
#else
#define USE_TC 0
#endif

// ---------------------------------------------------------------------------
// Problem constants
// ---------------------------------------------------------------------------
constexpr int Pn   = 48 * 48;   // 2304
constexpr int CX_  = 512;
constexpr int CF_  = 256;
constexpr int HID_ = 256;
constexpr int OUT_ = 512;
constexpr int BN_  = 16;

// ---------------------------------------------------------------------------
// Scratch (device globals; no allocation allowed). Everything K-major for its
// consumer GEMM.
// ---------------------------------------------------------------------------
__device__ float g_mvT[(size_t)BN_ * Pn * CX_];   // [z][p][cx]
__device__ float g_ffT[(size_t)4   * Pn * CF_];   // [b][p][cf]
__device__ float g_Q1t[(size_t)BN_ * Pn * HID_];  // [z][p][h]
__device__ float g_K1t[(size_t)4   * Pn * HID_];
__device__ float g_Q2t[(size_t)4   * Pn * HID_];
__device__ float g_K2t[(size_t)BN_ * Pn * HID_];
__device__ float g_S  [(size_t)BN_ * Pn * Pn];    // scores/attn (both layers)
__device__ float g_WRT[(size_t)BN_ * Pn * CF_];   // [z][p][cf]
__device__ float g_WLT[(size_t)BN_ * Pn * CX_];   // [z][p][cx]

// ---------------------------------------------------------------------------
// PTX helpers
// ---------------------------------------------------------------------------
__device__ __forceinline__ uint32_t smem_u32(const void* p) {
    uint32_t a;
    asm("{ .reg .u64 t; cvta.to.shared.u64 t, %1; cvt.u32.u64 %0, t; }"
        : "=r"(a) : "l"(p));
    return a;
}

// Pack (x -> lower bf16, y -> upper bf16). First PTX source fills the upper half.
__device__ __forceinline__ uint32_t pack_bf16x2(float x, float y) {
    uint32_t r;
    asm("cvt.rn.bf16x2.f32 %0, %1, %2;" : "=r"(r) : "f"(y), "f"(x));
    return r;
}
// Triple bf16 split of a (k-even, k-odd) pair: x = x1+x2+x3 + O(2^-27 x).
// Residuals x - bf16(x) are exact in fp32.
__device__ __forceinline__ void split3(float x, float y,
                                       uint32_t& p1, uint32_t& p2, uint32_t& p3) {
    p1 = pack_bf16x2(x, y);
    float rx = x - __uint_as_float(p1 << 16);
    float ry = y - __uint_as_float(p1 & 0xffff0000u);
    p2 = pack_bf16x2(rx, ry);
    float sx = rx - __uint_as_float(p2 << 16);
    float sy = ry - __uint_as_float(p2 & 0xffff0000u);
    p3 = pack_bf16x2(sx, sy);
}

#define MBAR_INIT(a, c) \
    asm volatile("mbarrier.init.shared.b64 [%0], %1;" :: "r"(a), "r"(c) : "memory")
#define MBAR_ARRIVE(a) \
    asm volatile("mbarrier.arrive.shared.b64 _, [%0];" :: "r"(a) : "memory")
#define MBAR_WAIT(a, ph) do {                                                  \
    uint32_t _m = (a), _p = (ph), _d = 0;                                      \
    while (!_d) {                                                              \
        asm volatile("{\n\t.reg .pred p;\n\t"                                  \
            "mbarrier.try_wait.parity.acquire.cta.shared::cta.b64 p, [%1], %2, 0x989680;\n\t" \
            "selp.b32 %0, 1, 0, p;\n\t}"                                       \
            : "=r"(_d) : "r"(_m), "r"(_p) : "memory");                         \
    } } while (0)

#define TC_ALLOC(sa, nc) \
    asm volatile("tcgen05.alloc.cta_group::1.sync.aligned.shared::cta.b32 [%0], %1;" \
        :: "r"(sa), "r"((uint32_t)(nc)) : "memory")
#define TC_RELINQ() \
    asm volatile("tcgen05.relinquish_alloc_permit.cta_group::1.sync.aligned;")
#define TC_DEALLOC(tm, nc) \
    asm volatile("tcgen05.dealloc.cta_group::1.sync.aligned.b32 %0, %1;" \
        :: "r"(tm), "r"((uint32_t)(nc)))
#define TC_COMMIT(mb) \
    asm volatile("tcgen05.commit.cta_group::1.mbarrier::arrive::one.shared::cluster.b64 [%0];" \
        :: "r"(mb) : "memory")
#define TC_FENCE_AFTER() asm volatile("tcgen05.fence::after_thread_sync;" ::: "memory")
#define TC_WAIT_LD()     asm volatile("tcgen05.wait::ld.sync.aligned;" ::: "memory")
#define FENCE_ASYNC()    asm volatile("fence.proxy.async.shared::cta;" ::: "memory")

#define TC_LD_X32(r, ta) \
    asm volatile("tcgen05.ld.sync.aligned.32x32b.x32.b32 " \
        "{%0,%1,%2,%3,%4,%5,%6,%7,%8,%9,%10,%11,%12,%13,%14,%15," \
        "%16,%17,%18,%19,%20,%21,%22,%23,%24,%25,%26,%27,%28,%29,%30,%31}, [%32];" \
        : "=r"((r)[0]),"=r"((r)[1]),"=r"((r)[2]),"=r"((r)[3]),   \
          "=r"((r)[4]),"=r"((r)[5]),"=r"((r)[6]),"=r"((r)[7]),   \
          "=r"((r)[8]),"=r"((r)[9]),"=r"((r)[10]),"=r"((r)[11]), \
          "=r"((r)[12]),"=r"((r)[13]),"=r"((r)[14]),"=r"((r)[15]),\
          "=r"((r)[16]),"=r"((r)[17]),"=r"((r)[18]),"=r"((r)[19]),\
          "=r"((r)[20]),"=r"((r)[21]),"=r"((r)[22]),"=r"((r)[23]),\
          "=r"((r)[24]),"=r"((r)[25]),"=r"((r)[26]),"=r"((r)[27]),\
          "=r"((r)[28]),"=r"((r)[29]),"=r"((r)[30]),"=r"((r)[31]) \
        : "r"(ta))

// idesc for kind::f16 bf16xbf16->f32: dtype F32 (1<<4), atype BF16 (1<<7),
// btype BF16 (1<<10), N=128 ((N/8)<<17), M=128 ((M/16)<<24)
constexpr uint32_t IDESC_BF16 =
    (1u << 4) | (1u << 7) | (1u << 10) | ((128u / 8) << 17) | ((128u / 16) << 24);

__device__ __forceinline__ void mma_bf16(uint32_t d, uint64_t ad, uint64_t bd, bool acc) {
    asm volatile("{\n\t.reg .pred p;\n\tsetp.ne.u32 p, %5, 0;\n\t"
        "tcgen05.mma.cta_group::1.kind::f16 [%0], %1, %2, %3, {%4,%4,%4,%4}, p;\n\t}"
        :: "r"(d), "l"(ad), "l"(bd), "r"(IDESC_BF16), "r"(0u), "r"(acc ? 1u : 0u)
        : "memory");
}

// SW128 K-major smem descriptor: layout=2, version=1, SBO=64, LBO=1
constexpr uint64_t DESC_BASE =
    (2ull << 61) | (1ull << 46) | (64ull << 32) | (1ull << 16);
__device__ __forceinline__ uint64_t sdesc(uint32_t addr) {
    return DESC_BASE | ((uint64_t)(addr >> 4) & 0x3FFFull);
}
__device__ __forceinline__ uint32_t sw128(uint32_t off) {
    return off ^ ((off >> 3) & 0x70);
}

// K-chunk 64 (bf16 -> 128B rows, SW128). Per stage: 6 term-tiles of 16KB
// (A1|A2|A3|B1|B2|B3). 2 stages = 192KB.
constexpr int TILE_B    = 16384;
constexpr int STAGE_B   = 6 * TILE_B;
constexpr int NSTAGE    = 2;
constexpr int SMEM_DYN  = 1024 + NSTAGE * STAGE_B + 1024;
constexpr int NTHREADS  = 288;   // 8 producer warps + 1 MMA warp

// ---------------------------------------------------------------------------
// Batched GEMM: D[m,n] = sum_k A[m,k] * B[n,k]; A,B fp32 K-major in gmem.
// Tile 128x128, K-chunk 64.  BIASM: 0 none, 1 bias[n], 2 bias[m].
// CONV: B rows gathered from concat(Bg=mvT | Bc1=WLT | Bc2=ffT | Bc3=WRT).
// Precision: bf16 triple-split (x = x1+x2+x3) with 6 products per k-step
// (x1y1, x1y2, x2y1, x2y2, x1y3, x3y1) -> method error ~2^-26, at the full
// bf16 tensor rate (tf32 runs at half rate -> this halves the MMA floor).
// Warp-specialized: warps 0-7 produce (LDG -> 3-term split -> swizzled STS
// -> 1 elected arrive/warp); warp 8 lane 0 issues 24 MMAs/chunk + commit.
// ---------------------------------------------------------------------------
template<int BIASM, bool CONV>
__global__ void __launch_bounds__(NTHREADS, 1)
tfgemm(const float* __restrict__ Ag, int lda, long long sA, int dA,
       const float* __restrict__ Bg, int ldb, long long sB, int dB,
       const float* __restrict__ Bc1, const float* __restrict__ Bc2,
       const float* __restrict__ Bc3,
       const float* __restrict__ bias,
       float* __restrict__ Cg, int ldc, long long sC, int K)
{
    extern __shared__ char smem[];
    const int tid  = threadIdx.x;
    const int z    = blockIdx.z;
    const int m0   = blockIdx.y * 128;
    const int n0   = blockIdx.x * 128;

    const uint32_t sbase = smem_u32(smem);
    const uint32_t data  = (sbase + 64 + 1023) & ~1023u;
    char* dptr = smem + (data - sbase);

    const float* A = Ag + (long long)(z / dA) * sA;

    auto bsel = [&](int kc, const float*& bp, int& bld, int& bkc) {
        if (!CONV) {
            bp = Bg + (long long)(z / dB) * sB; bld = ldb; bkc = kc;
        } else {
            if      (kc < 512)  { bp = Bg  + (long long)z * ((long long)Pn * 512);        bld = 512; bkc = kc; }
            else if (kc < 1024) { bp = Bc1 + (long long)z * ((long long)Pn * 512);        bld = 512; bkc = kc - 512; }
            else if (kc < 1280) { bp = Bc2 + (long long)(z >> 2) * ((long long)Pn * 256); bld = 256; bkc = kc - 1024; }
            else                { bp = Bc3 + (long long)z * ((long long)Pn * 256);        bld = 256; bkc = kc - 1280; }
        }
    };

#if USE_TC
    // ======================= tcgen05 fast path (sm_103a) ====================
    const int nk   = K >> 6;            // chunks of K=64
    const int wid  = tid >> 5;
    const int lane = tid & 31;
    const uint32_t hdr   = sbase;
    const uint32_t full0 = hdr + 8;     // NSTAGE mbarriers, 8 arrivals each
    const uint32_t free0 = hdr + 32;    // NSTAGE mbarriers, 1 arrival (commit)

    if (wid == 8) { TC_ALLOC(hdr, 128); TC_RELINQ(); }
    if (tid == 0) {
        #pragma unroll
        for (int s = 0; s < NSTAGE; ++s) {
            MBAR_INIT(full0 + 8u * s, 8);
            MBAR_INIT(free0 + 8u * s, 1);
        }
    }
    __syncthreads();
    uint32_t tmem;
    asm volatile("ld.shared.b32 %0, [%1];" : "=r"(tmem) : "r"(hdr));

    if (wid < 8) {
        // ---------------- producer warps (threads 0..255) ------------------
        // thread owns rows r0+32i (i<4), k-span c4*8..c4*8+7 (8 floats ->
        // 4 bf16x2 = 16B per term-tile per row)
        const int c4 = tid & 7;
        const int r0 = tid >> 3;
        uint32_t soff[4];
        #pragma unroll
        for (int i = 0; i < 4; ++i)
            soff[i] = sw128((uint32_t)((r0 + i * 32) * 128 + c4 * 16));
        const float* aptr = A + (size_t)(m0 + r0) * lda + c4 * 8;
        const size_t  astr = (size_t)32 * lda;
        const float* bptr0 = nullptr;
        size_t bstr = 0;
        if (!CONV) {
            bptr0 = Bg + (long long)(z / dB) * sB + (size_t)(n0 + r0) * ldb + c4 * 8;
            bstr  = (size_t)32 * ldb;
        }

        for (int ch = 0; ch < nk; ++ch) {
            const int kc = ch << 6;

            // issue all 16 LDG.128 first (latency overlaps the free-wait)
            float4 va[8], vb[8];
            #pragma unroll
            for (int i = 0; i < 4; ++i) {
                const float* ar = aptr + kc + (size_t)i * astr;
                va[2 * i]     = *reinterpret_cast<const float4*>(ar);
                va[2 * i + 1] = *reinterpret_cast<const float4*>(ar + 4);
            }
            if (!CONV) {
                #pragma unroll
                for (int i = 0; i < 4; ++i) {
                    const float* br = bptr0 + kc + (size_t)i * bstr;
                    vb[2 * i]     = *reinterpret_cast<const float4*>(br);
                    vb[2 * i + 1] = *reinterpret_cast<const float4*>(br + 4);
                }
            } else {
                const float* bp; int bld, bkc;
                bsel(kc, bp, bld, bkc);
                const float* bt = bp + (size_t)(n0 + r0) * bld + bkc + c4 * 8;
                #pragma unroll
                for (int i = 0; i < 4; ++i) {
                    const float* br = bt + (size_t)i * 32 * bld;
                    vb[2 * i]     = *reinterpret_cast<const float4*>(br);
                    vb[2 * i + 1] = *reinterpret_cast<const float4*>(br + 4);
                }
            }

            const int ps = ch & 1;
            const int rr = ch >> 1;
            if (rr > 0) MBAR_WAIT(free0 + 8u * ps, (rr - 1) & 1);

            char* stg = dptr + ps * STAGE_B;
            #pragma unroll
            for (int i = 0; i < 4; ++i) {
                uint4 t1, t2, t3;
                split3(va[2*i].x,   va[2*i].y,   t1.x, t2.x, t3.x);
                split3(va[2*i].z,   va[2*i].w,   t1.y, t2.y, t3.y);
                split3(va[2*i+1].x, va[2*i+1].y, t1.z, t2.z, t3.z);
                split3(va[2*i+1].z, va[2*i+1].w, t1.w, t2.w, t3.w);
                *reinterpret_cast<uint4*>(stg + 0 * TILE_B + soff[i]) = t1;
                *reinterpret_cast<uint4*>(stg + 1 * TILE_B + soff[i]) = t2;
                *reinterpret_cast<uint4*>(stg + 2 * TILE_B + soff[i]) = t3;
            }
            #pragma unroll
            for (int i = 0; i < 4; ++i) {
                uint4 t1, t2, t3;
                split3(vb[2*i].x,   vb[2*i].y,   t1.x, t2.x, t3.x);
                split3(vb[2*i].z,   vb[2*i].w,   t1.y, t2.y, t3.y);
                split3(vb[2*i+1].x, vb[2*i+1].y, t1.z, t2.z, t3.z);
                split3(vb[2*i+1].z, vb[2*i+1].w, t1.w, t2.w, t3.w);
                *reinterpret_cast<uint4*>(stg + 3 * TILE_B + soff[i]) = t1;
                *reinterpret_cast<uint4*>(stg + 4 * TILE_B + soff[i]) = t2;
                *reinterpret_cast<uint4*>(stg + 5 * TILE_B + soff[i]) = t3;
            }

            __syncwarp();
            if (lane == 0) MBAR_ARRIVE(full0 + 8u * ps);
        }
    } else if (lane == 0) {
        // ---------------- MMA issuer (warp 8, lane 0) ----------------------
        for (int ch = 0; ch < nk; ++ch) {
            const int ps = ch & 1;
            const int rr = ch >> 1;
            MBAR_WAIT(full0 + 8u * ps, rr & 1);
            FENCE_ASYNC();
            uint32_t sb = data + ps * STAGE_B;
            uint64_t a1 = sdesc(sb);
            uint64_t a2 = sdesc(sb + 1 * TILE_B);
            uint64_t a3 = sdesc(sb + 2 * TILE_B);
            uint64_t b1 = sdesc(sb + 3 * TILE_B);
            uint64_t b2 = sdesc(sb + 4 * TILE_B);
            uint64_t b3 = sdesc(sb + 5 * TILE_B);
            #pragma unroll
            for (int ks = 0; ks < 4; ++ks) {       // 4 k-steps of K=16
                uint64_t o = (uint64_t)(ks * 2);   // 32B per k-step
                mma_bf16(tmem, a1 + o, b1 + o, !(ch == 0 && ks == 0));
                mma_bf16(tmem, a1 + o, b2 + o, true);
                mma_bf16(tmem, a2 + o, b1 + o, true);
                mma_bf16(tmem, a2 + o, b2 + o, true);
                mma_bf16(tmem, a1 + o, b3 + o, true);
                mma_bf16(tmem, a3 + o, b1 + o, true);
            }
            TC_COMMIT(free0 + 8u * ps);
        }
    }

    // ---- epilogue (warps 0-7): wait final commit, TMEM -> smem -> gmem ----
    if (wid < 8) {
        MBAR_WAIT(free0 + 8u * ((nk - 1) & 1), ((nk - 1) >> 1) & 1);
        TC_FENCE_AFTER();

        float* sbuf = reinterpret_cast<float*>(dptr);  // 128 x 132 floats
        const int rsub = (wid & 3) * 32 + lane;
        const int g0   = (wid >> 2) * 2;

        #pragma unroll
        for (int gi = 0; gi < 2; ++gi) {
            const int g = g0 + gi;
            uint32_t r[32];
            TC_LD_X32(r, tmem + g * 32);
            TC_WAIT_LD();
            float rowb = (BIASM == 2) ? bias[m0 + rsub] : 0.0f;
            #pragma unroll
            for (int cc = 0; cc < 8; ++cc) {
                float4 v;
                v.x = __uint_as_float(r[cc * 4 + 0]);
                v.y = __uint_as_float(r[cc * 4 + 1]);
                v.z = __uint_as_float(r[cc * 4 + 2]);
                v.w = __uint_as_float(r[cc * 4 + 3]);
                if (BIASM == 1) {
                    float4 bv = *reinterpret_cast<const float4*>(bias + n0 + g * 32 + cc * 4);
                    v.x += bv.x; v.y += bv.y; v.z += bv.z; v.w += bv.w;
                } else if (BIASM == 2) {
                    v.x += rowb; v.y += rowb; v.z += rowb; v.w += rowb;
                }
                *reinterpret_cast<float4*>(&sbuf[rsub * 132 + g * 32 + cc * 4]) = v;
            }
        }
    }
    __syncthreads();

    if (wid < 8) {
        float* sbuf = reinterpret_cast<float*>(dptr);
        float* C = Cg + (long long)z * sC;
        #pragma unroll
        for (int i = 0; i < 16; ++i) {
            int u   = tid + i * 256;
            int row = u >> 5, cc = u & 31;
            float4 v = *reinterpret_cast<const float4*>(&sbuf[row * 132 + cc * 4]);
            *reinterpret_cast<float4*>(C + (size_t)(m0 + row) * ldc + n0 + cc * 4) = v;
        }
    }

    __syncthreads();
    if (wid == 8) TC_DEALLOC(tmem, 128);

#else
    // ================== portable FFMA fallback (plain sm_103) ===============
    const int nk32 = K >> 5;
    float* As2 = reinterpret_cast<float*>(dptr);
    float* Bs2 = As2 + 32 * 128;

    const int tx = tid & 15, ty = tid >> 4;
    float acc[8][8];
    #pragma unroll
    for (int i = 0; i < 8; ++i)
        #pragma unroll
        for (int j = 0; j < 8; ++j) acc[i][j] = 0.0f;

    for (int ch = 0; ch < nk32; ++ch) {
        const int kc = ch << 5;
        __syncthreads();
        if (tid < 256) {
            #pragma unroll
            for (int i = 0; i < 4; ++i) {
                int u = tid + i * 256;
                int row = u >> 3, cc = u & 7;
                float4 v = *reinterpret_cast<const float4*>(
                    A + (size_t)(m0 + row) * lda + kc + cc * 4);
                As2[(cc * 4 + 0) * 128 + row] = v.x;
                As2[(cc * 4 + 1) * 128 + row] = v.y;
                As2[(cc * 4 + 2) * 128 + row] = v.z;
                As2[(cc * 4 + 3) * 128 + row] = v.w;
            }
            const float* bp; int bld, bkc;
            bsel(kc, bp, bld, bkc);
            #pragma unroll
            for (int i = 0; i < 4; ++i) {
                int u = tid + i * 256;
                int row = u >> 3, cc = u & 7;
                float4 v = *reinterpret_cast<const float4*>(
                    bp + (size_t)(n0 + row) * bld + bkc + cc * 4);
                Bs2[(cc * 4 + 0) * 128 + row] = v.x;
                Bs2[(cc * 4 + 1) * 128 + row] = v.y;
                Bs2[(cc * 4 + 2) * 128 + row] = v.z;
                Bs2[(cc * 4 + 3) * 128 + row] = v.w;
            }
        }
        __syncthreads();
        if (tid < 256) {
            #pragma unroll
            for (int kk = 0; kk < 32; ++kk) {
                float a[8], b[8];
                #pragma unroll
                for (int i = 0; i < 4; ++i) {
                    a[i]     = As2[kk * 128 + ty * 4 + i];
                    a[i + 4] = As2[kk * 128 + 64 + ty * 4 + i];
                    b[i]     = Bs2[kk * 128 + tx * 4 + i];
                    b[i + 4] = Bs2[kk * 128 + 64 + tx * 4 + i];
                }
                #pragma unroll
                for (int i = 0; i < 8; ++i)
                    #pragma unroll
                    for (int j = 0; j < 8; ++j)
                        acc[i][j] = fmaf(a[i], b[j], acc[i][j]);
            }
        }
    }

    if (tid < 256) {
        float* C = Cg + (long long)z * sC;
        #pragma unroll
        for (int i = 0; i < 8; ++i) {
            const int m = m0 + ((i < 4) ? (ty * 4 + i) : (64 + ty * 4 + i - 4));
            const float rowb = (BIASM == 2) ? bias[m] : 0.0f;
            #pragma unroll
            for (int jh = 0; jh < 2; ++jh) {
                const int n = n0 + jh * 64 + tx * 4;
                float4 v;
                v.x = acc[i][jh * 4 + 0]; v.y = acc[i][jh * 4 + 1];
                v.z = acc[i][jh * 4 + 2]; v.w = acc[i][jh * 4 + 3];
                if (BIASM == 1) {
                    float4 bv = *reinterpret_cast<const float4*>(bias + n);
                    v.x += bv.x; v.y += bv.y; v.z += bv.z; v.w += bv.w;
                } else if (BIASM == 2) {
                    v.x += rowb; v.y += rowb; v.z += rowb; v.w += rowb;
                }
                *reinterpret_cast<float4*>(C + (size_t)m * ldc + n) = v;
            }
        }
    }
#endif
}

// ---------------------------------------------------------------------------
// 32x32 tiled transpose: src [z][C][Pn] -> dst [z][Pn][C]
// ---------------------------------------------------------------------------
__global__ void __launch_bounds__(256)
transp(const float* __restrict__ src, float* __restrict__ dst, int C)
{
    __shared__ float tile[32][33];
    const int p0 = blockIdx.x * 32, c0 = blockIdx.y * 32;
    const float* s = src + (size_t)blockIdx.z * C * Pn;
    float*       d = dst + (size_t)blockIdx.z * C * Pn;
    #pragma unroll
    for (int j = 0; j < 32; j += 8)
        tile[threadIdx.y + j][threadIdx.x] =
            s[(size_t)(c0 + threadIdx.y + j) * Pn + p0 + threadIdx.x];
    __syncthreads();
    #pragma unroll
    for (int j = 0; j < 32; j += 8)
        d[(size_t)(p0 + threadIdx.y + j) * C + c0 + threadIdx.x] =
            tile[threadIdx.x][threadIdx.y + j];
}

// ---------------------------------------------------------------------------
// Row softmax over g_S: grid (Pn, BN_), 256 threads, 9 elems/thread in regs
// ---------------------------------------------------------------------------
__global__ __launch_bounds__(256)
void softmax_rows(float* __restrict__ S)
{
    const int tid = threadIdx.x;
    const size_t base = ((size_t)blockIdx.y * Pn + blockIdx.x) * Pn;

    float r[9];
    float mx = -3.4e38f;
    #pragma unroll
    for (int j = 0; j < 9; ++j) {
        r[j] = S[base + tid + j * 256];
        mx = fmaxf(mx, r[j]);
    }
    __shared__ float sred[8];
    #pragma unroll
    for (int o = 16; o > 0; o >>= 1)
        mx = fmaxf(mx, __shfl_xor_sync(0xffffffffu, mx, o));
    if ((tid & 31) == 0) sred[tid >> 5] = mx;
    __syncthreads();
    mx = sred[0];
    #pragma unroll
    for (int w = 1; w < 8; ++w) mx = fmaxf(mx, sred[w]);

    float s = 0.0f;
    #pragma unroll
    for (int j = 0; j < 9; ++j) { r[j] = __expf(r[j] - mx); s += r[j]; }
    #pragma unroll
    for (int o = 16; o > 0; o >>= 1)
        s += __shfl_xor_sync(0xffffffffu, s, o);
    __syncthreads();
    if ((tid & 31) == 0) sred[tid >> 5] = s;
    __syncthreads();
    s = 0.0f;
    #pragma unroll
    for (int w = 0; w < 8; ++w) s += sred[w];

    const float inv = 1.0f / s;
    #pragma unroll
    for (int j = 0; j < 9; ++j)
        S[base + tid + j * 256] = r[j] * inv;
}

// ---------------------------------------------------------------------------
// Launch sequence (default stream, graph-capturable)
// ---------------------------------------------------------------------------
extern "C" void kernel_launch(void* const* d_in, const int* in_sizes, int n_in,
                              void* d_out, int out_size)
{
    const float* mv  = (const float*)d_in[0];   // [16,512,P]
    const float* ff  = (const float*)d_in[1];   // [4,256,P]
    const float* wq1 = (const float*)d_in[2];
    const float* bq1 = (const float*)d_in[3];
    const float* wk1 = (const float*)d_in[4];
    const float* bk1 = (const float*)d_in[5];
    const float* wq2 = (const float*)d_in[6];
    const float* bq2 = (const float*)d_in[7];
    const float* wk2 = (const float*)d_in[8];
    const float* bk2 = (const float*)d_in[9];
    const float* wdr = (const float*)d_in[10];  // [512,1536]
    const float* bdr = (const float*)d_in[11];
    float* out = (float*)d_out;                 // [16,512,P]

    float *mvT, *ffT, *Q1t, *K1t, *Q2t, *K2t, *S, *WRT, *WLT;
    cudaGetSymbolAddress((void**)&mvT, g_mvT);
    cudaGetSymbolAddress((void**)&ffT, g_ffT);
    cudaGetSymbolAddress((void**)&Q1t, g_Q1t);
    cudaGetSymbolAddress((void**)&K1t, g_K1t);
    cudaGetSymbolAddress((void**)&Q2t, g_Q2t);
    cudaGetSymbolAddress((void**)&K2t, g_K2t);
    cudaGetSymbolAddress((void**)&S,   g_S);
    cudaGetSymbolAddress((void**)&WRT, g_WRT);
    cudaGetSymbolAddress((void**)&WLT, g_WLT);

    cudaFuncSetAttribute(tfgemm<0, false>, cudaFuncAttributeMaxDynamicSharedMemorySize, SMEM_DYN);
    cudaFuncSetAttribute(tfgemm<1, false>, cudaFuncAttributeMaxDynamicSharedMemorySize, SMEM_DYN);
    cudaFuncSetAttribute(tfgemm<2, true>,  cudaFuncAttributeMaxDynamicSharedMemorySize, SMEM_DYN);

    const long long sMVT = (long long)Pn * CX_;
    const long long sFFT = (long long)Pn * CF_;
    const long long sHT  = (long long)Pn * HID_;
    const long long sS   = (long long)Pn * Pn;
    const long long sWRT = (long long)Pn * CF_;
    const long long sWLT = (long long)Pn * CX_;
    const long long sO   = (long long)OUT_ * Pn;

    // transposes -> K-major inputs
    transp<<<dim3(Pn / 32, CX_ / 32, 16), dim3(32, 8)>>>(mv, mvT, CX_);
    transp<<<dim3(Pn / 32, CF_ / 32, 4),  dim3(32, 8)>>>(ff, ffT, CF_);

    // projections: D[p,h] = sum_c X[p,c] * W[h,c] + b[h]
    tfgemm<1, false><<<dim3(2, 18, 16), NTHREADS, SMEM_DYN>>>(
        mvT, CX_, sMVT, 1,  wq1, CX_, 0LL, 1,  nullptr, nullptr, nullptr,
        bq1,  Q1t, HID_, sHT, CX_);
    tfgemm<1, false><<<dim3(2, 18, 4), NTHREADS, SMEM_DYN>>>(
        ffT, CF_, sFFT, 1,  wk1, CF_, 0LL, 1,  nullptr, nullptr, nullptr,
        bk1,  K1t, HID_, sHT, CF_);
    tfgemm<1, false><<<dim3(2, 18, 4), NTHREADS, SMEM_DYN>>>(
        ffT, CF_, sFFT, 1,  wq2, CF_, 0LL, 1,  nullptr, nullptr, nullptr,
        bq2,  Q2t, HID_, sHT, CF_);
    tfgemm<1, false><<<dim3(2, 18, 16), NTHREADS, SMEM_DYN>>>(
        mvT, CX_, sMVT, 1,  wk2, CX_, 0LL, 1,  nullptr, nullptr, nullptr,
        bk2,  K2t, HID_, sHT, CX_);

    // layer 1: S[p,q] = Q1t[p,:].K1t[q,:]; softmax; WRT[p,c] = S[p,:].ff[c,:]
    tfgemm<0, false><<<dim3(18, 18, 16), NTHREADS, SMEM_DYN>>>(
        Q1t, HID_, sHT, 1,  K1t, HID_, sHT, 4,  nullptr, nullptr, nullptr,
        nullptr,  S, Pn, sS, HID_);
    softmax_rows<<<dim3(Pn, BN_), 256>>>(S);
    tfgemm<0, false><<<dim3(2, 18, 16), NTHREADS, SMEM_DYN>>>(
        S, Pn, sS, 1,  ff, Pn, (long long)CF_ * Pn, 4,  nullptr, nullptr, nullptr,
        nullptr,  WRT, CF_, sWRT, Pn);

    // layer 2
    tfgemm<0, false><<<dim3(18, 18, 16), NTHREADS, SMEM_DYN>>>(
        Q2t, HID_, sHT, 4,  K2t, HID_, sHT, 1,  nullptr, nullptr, nullptr,
        nullptr,  S, Pn, sS, HID_);
    softmax_rows<<<dim3(Pn, BN_), 256>>>(S);
    tfgemm<0, false><<<dim3(4, 18, 16), NTHREADS, SMEM_DYN>>>(
        S, Pn, sS, 1,  mv, Pn, (long long)CX_ * Pn, 1,  nullptr, nullptr, nullptr,
        nullptr,  WLT, CX_, sWLT, Pn);

    // fused conv: out[o,p] = sum_f wdr[o,f] * featT[p,f] + bdr[o], K=1536
    tfgemm<2, true><<<dim3(18, 4, 16), NTHREADS, SMEM_DYN>>>(
        wdr, 1536, 0LL, 1,  mvT, 0, 0LL, 1,  WLT, ffT, WRT,
        bdr,  out, Pn, sO, 1536);
}

// round 17
// speedup vs baseline: 1.6850x; 1.1502x over previous
#include <cuda_runtime.h>
#include <cstdint>

// ---------------------------------------------------------------------------
// Arch gate: tcgen05 only exists on the arch-specific (sm_103a) target. The
// harness also compiles a plain compute_103 target, which must fall back.
// ---------------------------------------------------------------------------
#if defined(__CUDA_ARCH_FEAT_SM103_ALL) || defined(__CUDA_ARCH_FEAT_SM100_ALL) || \
    defined(__CUDA_ARCH_SPECIFIC__) || defined(__CUDA_ARCH_FAMILY_SPECIFIC__)
#define USE_TC 1
#else
#define USE_TC 0
#endif

// ---------------------------------------------------------------------------
// Problem constants
// ---------------------------------------------------------------------------
constexpr int Pn   = 48 * 48;   // 2304
constexpr int CX_  = 512;
constexpr int CF_  = 256;
constexpr int HID_ = 256;
constexpr int OUT_ = 512;
constexpr int BN_  = 16;

// ---------------------------------------------------------------------------
// Scratch (device globals; no allocation allowed). Everything K-major for its
// consumer GEMM.
// ---------------------------------------------------------------------------
__device__ float g_mvT[(size_t)BN_ * Pn * CX_];   // [z][p][cx]
__device__ float g_ffT[(size_t)4   * Pn * CF_];   // [b][p][cf]
__device__ float g_Q1t[(size_t)BN_ * Pn * HID_];  // [z][p][h]
__device__ float g_K1t[(size_t)4   * Pn * HID_];
__device__ float g_Q2t[(size_t)4   * Pn * HID_];
__device__ float g_K2t[(size_t)BN_ * Pn * HID_];
__device__ float g_S  [(size_t)BN_ * Pn * Pn];    // scores/attn (both layers)
__device__ float g_WRT[(size_t)BN_ * Pn * CF_];   // [z][p][cf]
__device__ float g_WLT[(size_t)BN_ * Pn * CX_];   // [z][p][cx]

// ---------------------------------------------------------------------------
// PTX helpers
// ---------------------------------------------------------------------------
__device__ __forceinline__ uint32_t smem_u32(const void* p) {
    uint32_t a;
    asm("{ .reg .u64 t; cvta.to.shared.u64 t, %1; cvt.u32.u64 %0, t; }"
        : "=r"(a) : "l"(p));
    return a;
}

// Pack (x -> lower bf16, y -> upper bf16). First PTX source fills the upper half.
__device__ __forceinline__ uint32_t pack_bf16x2(float x, float y) {
    uint32_t r;
    asm("cvt.rn.bf16x2.f32 %0, %1, %2;" : "=r"(r) : "f"(y), "f"(x));
    return r;
}
// Double bf16 split of a (k-even, k-odd) pair: x = x1 + x2 + O(2^-18 x).
// Residual x - bf16(x) is exact in fp32.
__device__ __forceinline__ void split2p(float x, float y,
                                        uint32_t& p1, uint32_t& p2) {
    p1 = pack_bf16x2(x, y);
    float rx = x - __uint_as_float(p1 << 16);
    float ry = y - __uint_as_float(p1 & 0xffff0000u);
    p2 = pack_bf16x2(rx, ry);
}

#define MBAR_INIT(a, c) \
    asm volatile("mbarrier.init.shared.b64 [%0], %1;" :: "r"(a), "r"(c) : "memory")
#define MBAR_ARRIVE(a) \
    asm volatile("mbarrier.arrive.shared.b64 _, [%0];" :: "r"(a) : "memory")
#define MBAR_WAIT(a, ph) do {                                                  \
    uint32_t _m = (a), _p = (ph), _d = 0;                                      \
    while (!_d) {                                                              \
        asm volatile("{\n\t.reg .pred p;\n\t"                                  \
            "mbarrier.try_wait.parity.acquire.cta.shared::cta.b64 p, [%1], %2, 0x989680;\n\t" \
            "selp.b32 %0, 1, 0, p;\n\t}"                                       \
            : "=r"(_d) : "r"(_m), "r"(_p) : "memory");                         \
    } } while (0)

#define TC_ALLOC(sa, nc) \
    asm volatile("tcgen05.alloc.cta_group::1.sync.aligned.shared::cta.b32 [%0], %1;" \
        :: "r"(sa), "r"((uint32_t)(nc)) : "memory")
#define TC_RELINQ() \
    asm volatile("tcgen05.relinquish_alloc_permit.cta_group::1.sync.aligned;")
#define TC_DEALLOC(tm, nc) \
    asm volatile("tcgen05.dealloc.cta_group::1.sync.aligned.b32 %0, %1;" \
        :: "r"(tm), "r"((uint32_t)(nc)))
#define TC_COMMIT(mb) \
    asm volatile("tcgen05.commit.cta_group::1.mbarrier::arrive::one.shared::cluster.b64 [%0];" \
        :: "r"(mb) : "memory")
#define TC_FENCE_AFTER() asm volatile("tcgen05.fence::after_thread_sync;" ::: "memory")
#define TC_WAIT_LD()     asm volatile("tcgen05.wait::ld.sync.aligned;" ::: "memory")
#define FENCE_ASYNC()    asm volatile("fence.proxy.async.shared::cta;" ::: "memory")

#define TC_LD_X32(r, ta) \
    asm volatile("tcgen05.ld.sync.aligned.32x32b.x32.b32 " \
        "{%0,%1,%2,%3,%4,%5,%6,%7,%8,%9,%10,%11,%12,%13,%14,%15," \
        "%16,%17,%18,%19,%20,%21,%22,%23,%24,%25,%26,%27,%28,%29,%30,%31}, [%32];" \
        : "=r"((r)[0]),"=r"((r)[1]),"=r"((r)[2]),"=r"((r)[3]),   \
          "=r"((r)[4]),"=r"((r)[5]),"=r"((r)[6]),"=r"((r)[7]),   \
          "=r"((r)[8]),"=r"((r)[9]),"=r"((r)[10]),"=r"((r)[11]), \
          "=r"((r)[12]),"=r"((r)[13]),"=r"((r)[14]),"=r"((r)[15]),\
          "=r"((r)[16]),"=r"((r)[17]),"=r"((r)[18]),"=r"((r)[19]),\
          "=r"((r)[20]),"=r"((r)[21]),"=r"((r)[22]),"=r"((r)[23]),\
          "=r"((r)[24]),"=r"((r)[25]),"=r"((r)[26]),"=r"((r)[27]),\
          "=r"((r)[28]),"=r"((r)[29]),"=r"((r)[30]),"=r"((r)[31]) \
        : "r"(ta))

// idesc for kind::f16 bf16xbf16->f32: dtype F32 (1<<4), atype BF16 (1<<7),
// btype BF16 (1<<10), N=128 ((N/8)<<17), M=128 ((M/16)<<24)
constexpr uint32_t IDESC_BF16 =
    (1u << 4) | (1u << 7) | (1u << 10) | ((128u / 8) << 17) | ((128u / 16) << 24);

__device__ __forceinline__ void mma_bf16(uint32_t d, uint64_t ad, uint64_t bd, bool acc) {
    asm volatile("{\n\t.reg .pred p;\n\tsetp.ne.u32 p, %5, 0;\n\t"
        "tcgen05.mma.cta_group::1.kind::f16 [%0], %1, %2, %3, {%4,%4,%4,%4}, p;\n\t}"
        :: "r"(d), "l"(ad), "l"(bd), "r"(IDESC_BF16), "r"(0u), "r"(acc ? 1u : 0u)
        : "memory");
}

// SW128 K-major smem descriptor: layout=2, version=1, SBO=64, LBO=1
constexpr uint64_t DESC_BASE =
    (2ull << 61) | (1ull << 46) | (64ull << 32) | (1ull << 16);
__device__ __forceinline__ uint64_t sdesc(uint32_t addr) {
    return DESC_BASE | ((uint64_t)(addr >> 4) & 0x3FFFull);
}
__device__ __forceinline__ uint32_t sw128(uint32_t off) {
    return off ^ ((off >> 3) & 0x70);
}

// K-chunk 64 (bf16 -> 128B rows, SW128). Per stage: 4 term-tiles of 16KB
// (A1|A2|B1|B2). 3 stages = 192KB.
constexpr int TILE_B    = 16384;
constexpr int STAGE_B   = 4 * TILE_B;
constexpr int NSTAGE    = 3;
constexpr int SMEM_DYN  = 1024 + NSTAGE * STAGE_B + 1024;
constexpr int NTHREADS  = 288;   // 8 producer warps + 1 MMA warp

// ---------------------------------------------------------------------------
// Batched GEMM: D[m,n] = sum_k A[m,k] * B[n,k]; A,B fp32 K-major in gmem.
// Tile 128x128, K-chunk 64.  BIASM: 0 none, 1 bias[n], 2 bias[m].
// CONV: B rows gathered from concat(Bg=mvT | Bc1=WLT | Bc2=ffT | Bc3=WRT).
// Precision: bf16 double-split (x = x1+x2, residual 2^-18) with 3 products
// per k-step (x1y1, x1y2, x2y1); dropped x2y2 ~2^-18 -> dot-product relative
// error ~1e-5, ~100x inside the 1e-3 budget. Per-dispatch tensor cost is
// dtype-independent (64 cyc @ N=128), so 3 bf16 terms (K=16 each) = half the
// MMA floor of tf32x3 / bf16x6.
// Warp-specialized: warps 0-7 produce (LDG -> 2-term split -> swizzled STS
// -> 1 elected arrive/warp); warp 8 lane 0 issues 12 MMAs/chunk + commit.
// ---------------------------------------------------------------------------
template<int BIASM, bool CONV>
__global__ void __launch_bounds__(NTHREADS, 1)
tfgemm(const float* __restrict__ Ag, int lda, long long sA, int dA,
       const float* __restrict__ Bg, int ldb, long long sB, int dB,
       const float* __restrict__ Bc1, const float* __restrict__ Bc2,
       const float* __restrict__ Bc3,
       const float* __restrict__ bias,
       float* __restrict__ Cg, int ldc, long long sC, int K)
{
    extern __shared__ char smem[];
    const int tid  = threadIdx.x;
    const int z    = blockIdx.z;
    const int m0   = blockIdx.y * 128;
    const int n0   = blockIdx.x * 128;

    const uint32_t sbase = smem_u32(smem);
    const uint32_t data  = (sbase + 64 + 1023) & ~1023u;
    char* dptr = smem + (data - sbase);

    const float* A = Ag + (long long)(z / dA) * sA;

    auto bsel = [&](int kc, const float*& bp, int& bld, int& bkc) {
        if (!CONV) {
            bp = Bg + (long long)(z / dB) * sB; bld = ldb; bkc = kc;
        } else {
            if      (kc < 512)  { bp = Bg  + (long long)z * ((long long)Pn * 512);        bld = 512; bkc = kc; }
            else if (kc < 1024) { bp = Bc1 + (long long)z * ((long long)Pn * 512);        bld = 512; bkc = kc - 512; }
            else if (kc < 1280) { bp = Bc2 + (long long)(z >> 2) * ((long long)Pn * 256); bld = 256; bkc = kc - 1024; }
            else                { bp = Bc3 + (long long)z * ((long long)Pn * 256);        bld = 256; bkc = kc - 1280; }
        }
    };

#if USE_TC
    // ======================= tcgen05 fast path (sm_103a) ====================
    const int nk   = K >> 6;            // chunks of K=64
    const int wid  = tid >> 5;
    const int lane = tid & 31;
    const uint32_t hdr   = sbase;
    const uint32_t full0 = hdr + 8;     // NSTAGE mbarriers, 8 arrivals each
    const uint32_t free0 = hdr + 32;    // NSTAGE mbarriers, 1 arrival (commit)

    if (wid == 8) { TC_ALLOC(hdr, 128); TC_RELINQ(); }
    if (tid == 0) {
        #pragma unroll
        for (int s = 0; s < NSTAGE; ++s) {
            MBAR_INIT(full0 + 8u * s, 8);
            MBAR_INIT(free0 + 8u * s, 1);
        }
    }
    __syncthreads();
    uint32_t tmem;
    asm volatile("ld.shared.b32 %0, [%1];" : "=r"(tmem) : "r"(hdr));

    if (wid < 8) {
        // ---------------- producer warps (threads 0..255) ------------------
        // thread owns rows r0+32i (i<4), k-span c4*8..c4*8+7 (8 floats ->
        // 4 bf16x2 = 16B per term-tile per row)
        const int c4 = tid & 7;
        const int r0 = tid >> 3;
        uint32_t soff[4];
        #pragma unroll
        for (int i = 0; i < 4; ++i)
            soff[i] = sw128((uint32_t)((r0 + i * 32) * 128 + c4 * 16));
        const float* aptr = A + (size_t)(m0 + r0) * lda + c4 * 8;
        const size_t  astr = (size_t)32 * lda;
        const float* bptr0 = nullptr;
        size_t bstr = 0;
        if (!CONV) {
            bptr0 = Bg + (long long)(z / dB) * sB + (size_t)(n0 + r0) * ldb + c4 * 8;
            bstr  = (size_t)32 * ldb;
        }

        for (int ch = 0; ch < nk; ++ch) {
            const int kc = ch << 6;

            // issue all 16 LDG.128 first (latency overlaps the free-wait)
            float4 va[8], vb[8];
            #pragma unroll
            for (int i = 0; i < 4; ++i) {
                const float* ar = aptr + kc + (size_t)i * astr;
                va[2 * i]     = *reinterpret_cast<const float4*>(ar);
                va[2 * i + 1] = *reinterpret_cast<const float4*>(ar + 4);
            }
            if (!CONV) {
                #pragma unroll
                for (int i = 0; i < 4; ++i) {
                    const float* br = bptr0 + kc + (size_t)i * bstr;
                    vb[2 * i]     = *reinterpret_cast<const float4*>(br);
                    vb[2 * i + 1] = *reinterpret_cast<const float4*>(br + 4);
                }
            } else {
                const float* bp; int bld, bkc;
                bsel(kc, bp, bld, bkc);
                const float* bt = bp + (size_t)(n0 + r0) * bld + bkc + c4 * 8;
                #pragma unroll
                for (int i = 0; i < 4; ++i) {
                    const float* br = bt + (size_t)i * 32 * bld;
                    vb[2 * i]     = *reinterpret_cast<const float4*>(br);
                    vb[2 * i + 1] = *reinterpret_cast<const float4*>(br + 4);
                }
            }

            const int ps = ch % NSTAGE;
            const int rr = ch / NSTAGE;
            if (rr > 0) MBAR_WAIT(free0 + 8u * ps, (rr - 1) & 1);

            char* stg = dptr + ps * STAGE_B;
            #pragma unroll
            for (int i = 0; i < 4; ++i) {
                uint4 t1, t2;
                split2p(va[2*i].x,   va[2*i].y,   t1.x, t2.x);
                split2p(va[2*i].z,   va[2*i].w,   t1.y, t2.y);
                split2p(va[2*i+1].x, va[2*i+1].y, t1.z, t2.z);
                split2p(va[2*i+1].z, va[2*i+1].w, t1.w, t2.w);
                *reinterpret_cast<uint4*>(stg + 0 * TILE_B + soff[i]) = t1;
                *reinterpret_cast<uint4*>(stg + 1 * TILE_B + soff[i]) = t2;
            }
            #pragma unroll
            for (int i = 0; i < 4; ++i) {
                uint4 t1, t2;
                split2p(vb[2*i].x,   vb[2*i].y,   t1.x, t2.x);
                split2p(vb[2*i].z,   vb[2*i].w,   t1.y, t2.y);
                split2p(vb[2*i+1].x, vb[2*i+1].y, t1.z, t2.z);
                split2p(vb[2*i+1].z, vb[2*i+1].w, t1.w, t2.w);
                *reinterpret_cast<uint4*>(stg + 2 * TILE_B + soff[i]) = t1;
                *reinterpret_cast<uint4*>(stg + 3 * TILE_B + soff[i]) = t2;
            }

            __syncwarp();
            if (lane == 0) MBAR_ARRIVE(full0 + 8u * ps);
        }
    } else if (lane == 0) {
        // ---------------- MMA issuer (warp 8, lane 0) ----------------------
        for (int ch = 0; ch < nk; ++ch) {
            const int ps = ch % NSTAGE;
            const int rr = ch / NSTAGE;
            MBAR_WAIT(full0 + 8u * ps, rr & 1);
            FENCE_ASYNC();
            uint32_t sb = data + ps * STAGE_B;
            uint64_t a1 = sdesc(sb);
            uint64_t a2 = sdesc(sb + 1 * TILE_B);
            uint64_t b1 = sdesc(sb + 2 * TILE_B);
            uint64_t b2 = sdesc(sb + 3 * TILE_B);
            #pragma unroll
            for (int ks = 0; ks < 4; ++ks) {       // 4 k-steps of K=16
                uint64_t o = (uint64_t)(ks * 2);   // 32B per k-step
                mma_bf16(tmem, a1 + o, b1 + o, !(ch == 0 && ks == 0));
                mma_bf16(tmem, a1 + o, b2 + o, true);
                mma_bf16(tmem, a2 + o, b1 + o, true);
            }
            TC_COMMIT(free0 + 8u * ps);
        }
    }

    // ---- epilogue (warps 0-7): wait final commit, TMEM -> smem -> gmem ----
    if (wid < 8) {
        MBAR_WAIT(free0 + 8u * ((nk - 1) % NSTAGE), ((nk - 1) / NSTAGE) & 1);
        TC_FENCE_AFTER();

        float* sbuf = reinterpret_cast<float*>(dptr);  // 128 x 132 floats
        const int rsub = (wid & 3) * 32 + lane;
        const int g0   = (wid >> 2) * 2;

        #pragma unroll
        for (int gi = 0; gi < 2; ++gi) {
            const int g = g0 + gi;
            uint32_t r[32];
            TC_LD_X32(r, tmem + g * 32);
            TC_WAIT_LD();
            float rowb = (BIASM == 2) ? bias[m0 + rsub] : 0.0f;
            #pragma unroll
            for (int cc = 0; cc < 8; ++cc) {
                float4 v;
                v.x = __uint_as_float(r[cc * 4 + 0]);
                v.y = __uint_as_float(r[cc * 4 + 1]);
                v.z = __uint_as_float(r[cc * 4 + 2]);
                v.w = __uint_as_float(r[cc * 4 + 3]);
                if (BIASM == 1) {
                    float4 bv = *reinterpret_cast<const float4*>(bias + n0 + g * 32 + cc * 4);
                    v.x += bv.x; v.y += bv.y; v.z += bv.z; v.w += bv.w;
                } else if (BIASM == 2) {
                    v.x += rowb; v.y += rowb; v.z += rowb; v.w += rowb;
                }
                *reinterpret_cast<float4*>(&sbuf[rsub * 132 + g * 32 + cc * 4]) = v;
            }
        }
    }
    __syncthreads();

    if (wid < 8) {
        float* sbuf = reinterpret_cast<float*>(dptr);
        float* C = Cg + (long long)z * sC;
        #pragma unroll
        for (int i = 0; i < 16; ++i) {
            int u   = tid + i * 256;
            int row = u >> 5, cc = u & 31;
            float4 v = *reinterpret_cast<const float4*>(&sbuf[row * 132 + cc * 4]);
            *reinterpret_cast<float4*>(C + (size_t)(m0 + row) * ldc + n0 + cc * 4) = v;
        }
    }

    __syncthreads();
    if (wid == 8) TC_DEALLOC(tmem, 128);

#else
    // ================== portable FFMA fallback (plain sm_103) ===============
    const int nk32 = K >> 5;
    float* As2 = reinterpret_cast<float*>(dptr);
    float* Bs2 = As2 + 32 * 128;

    const int tx = tid & 15, ty = tid >> 4;
    float acc[8][8];
    #pragma unroll
    for (int i = 0; i < 8; ++i)
        #pragma unroll
        for (int j = 0; j < 8; ++j) acc[i][j] = 0.0f;

    for (int ch = 0; ch < nk32; ++ch) {
        const int kc = ch << 5;
        __syncthreads();
        if (tid < 256) {
            #pragma unroll
            for (int i = 0; i < 4; ++i) {
                int u = tid + i * 256;
                int row = u >> 3, cc = u & 7;
                float4 v = *reinterpret_cast<const float4*>(
                    A + (size_t)(m0 + row) * lda + kc + cc * 4);
                As2[(cc * 4 + 0) * 128 + row] = v.x;
                As2[(cc * 4 + 1) * 128 + row] = v.y;
                As2[(cc * 4 + 2) * 128 + row] = v.z;
                As2[(cc * 4 + 3) * 128 + row] = v.w;
            }
            const float* bp; int bld, bkc;
            bsel(kc, bp, bld, bkc);
            #pragma unroll
            for (int i = 0; i < 4; ++i) {
                int u = tid + i * 256;
                int row = u >> 3, cc = u & 7;
                float4 v = *reinterpret_cast<const float4*>(
                    bp + (size_t)(n0 + row) * bld + bkc + cc * 4);
                Bs2[(cc * 4 + 0) * 128 + row] = v.x;
                Bs2[(cc * 4 + 1) * 128 + row] = v.y;
                Bs2[(cc * 4 + 2) * 128 + row] = v.z;
                Bs2[(cc * 4 + 3) * 128 + row] = v.w;
            }
        }
        __syncthreads();
        if (tid < 256) {
            #pragma unroll
            for (int kk = 0; kk < 32; ++kk) {
                float a[8], b[8];
                #pragma unroll
                for (int i = 0; i < 4; ++i) {
                    a[i]     = As2[kk * 128 + ty * 4 + i];
                    a[i + 4] = As2[kk * 128 + 64 + ty * 4 + i];
                    b[i]     = Bs2[kk * 128 + tx * 4 + i];
                    b[i + 4] = Bs2[kk * 128 + 64 + tx * 4 + i];
                }
                #pragma unroll
                for (int i = 0; i < 8; ++i)
                    #pragma unroll
                    for (int j = 0; j < 8; ++j)
                        acc[i][j] = fmaf(a[i], b[j], acc[i][j]);
            }
        }
    }

    if (tid < 256) {
        float* C = Cg + (long long)z * sC;
        #pragma unroll
        for (int i = 0; i < 8; ++i) {
            const int m = m0 + ((i < 4) ? (ty * 4 + i) : (64 + ty * 4 + i - 4));
            const float rowb = (BIASM == 2) ? bias[m] : 0.0f;
            #pragma unroll
            for (int jh = 0; jh < 2; ++jh) {
                const int n = n0 + jh * 64 + tx * 4;
                float4 v;
                v.x = acc[i][jh * 4 + 0]; v.y = acc[i][jh * 4 + 1];
                v.z = acc[i][jh * 4 + 2]; v.w = acc[i][jh * 4 + 3];
                if (BIASM == 1) {
                    float4 bv = *reinterpret_cast<const float4*>(bias + n);
                    v.x += bv.x; v.y += bv.y; v.z += bv.z; v.w += bv.w;
                } else if (BIASM == 2) {
                    v.x += rowb; v.y += rowb; v.z += rowb; v.w += rowb;
                }
                *reinterpret_cast<float4*>(C + (size_t)m * ldc + n) = v;
            }
        }
    }
#endif
}

// ---------------------------------------------------------------------------
// 32x32 tiled transpose: src [z][C][Pn] -> dst [z][Pn][C]
// ---------------------------------------------------------------------------
__global__ void __launch_bounds__(256)
transp(const float* __restrict__ src, float* __restrict__ dst, int C)
{
    __shared__ float tile[32][33];
    const int p0 = blockIdx.x * 32, c0 = blockIdx.y * 32;
    const float* s = src + (size_t)blockIdx.z * C * Pn;
    float*       d = dst + (size_t)blockIdx.z * C * Pn;
    #pragma unroll
    for (int j = 0; j < 32; j += 8)
        tile[threadIdx.y + j][threadIdx.x] =
            s[(size_t)(c0 + threadIdx.y + j) * Pn + p0 + threadIdx.x];
    __syncthreads();
    #pragma unroll
    for (int j = 0; j < 32; j += 8)
        d[(size_t)(p0 + threadIdx.y + j) * C + c0 + threadIdx.x] =
            tile[threadIdx.x][threadIdx.y + j];
}

// ---------------------------------------------------------------------------
// Row softmax over g_S: grid (Pn, BN_), 256 threads, 9 elems/thread in regs
// ---------------------------------------------------------------------------
__global__ __launch_bounds__(256)
void softmax_rows(float* __restrict__ S)
{
    const int tid = threadIdx.x;
    const size_t base = ((size_t)blockIdx.y * Pn + blockIdx.x) * Pn;

    float r[9];
    float mx = -3.4e38f;
    #pragma unroll
    for (int j = 0; j < 9; ++j) {
        r[j] = S[base + tid + j * 256];
        mx = fmaxf(mx, r[j]);
    }
    __shared__ float sred[8];
    #pragma unroll
    for (int o = 16; o > 0; o >>= 1)
        mx = fmaxf(mx, __shfl_xor_sync(0xffffffffu, mx, o));
    if ((tid & 31) == 0) sred[tid >> 5] = mx;
    __syncthreads();
    mx = sred[0];
    #pragma unroll
    for (int w = 1; w < 8; ++w) mx = fmaxf(mx, sred[w]);

    float s = 0.0f;
    #pragma unroll
    for (int j = 0; j < 9; ++j) { r[j] = __expf(r[j] - mx); s += r[j]; }
    #pragma unroll
    for (int o = 16; o > 0; o >>= 1)
        s += __shfl_xor_sync(0xffffffffu, s, o);
    __syncthreads();
    if ((tid & 31) == 0) sred[tid >> 5] = s;
    __syncthreads();
    s = 0.0f;
    #pragma unroll
    for (int w = 0; w < 8; ++w) s += sred[w];

    const float inv = 1.0f / s;
    #pragma unroll
    for (int j = 0; j < 9; ++j)
        S[base + tid + j * 256] = r[j] * inv;
}

// ---------------------------------------------------------------------------
// Launch sequence (default stream, graph-capturable)
// ---------------------------------------------------------------------------
extern "C" void kernel_launch(void* const* d_in, const int* in_sizes, int n_in,
                              void* d_out, int out_size)
{
    const float* mv  = (const float*)d_in[0];   // [16,512,P]
    const float* ff  = (const float*)d_in[1];   // [4,256,P]
    const float* wq1 = (const float*)d_in[2];
    const float* bq1 = (const float*)d_in[3];
    const float* wk1 = (const float*)d_in[4];
    const float* bk1 = (const float*)d_in[5];
    const float* wq2 = (const float*)d_in[6];
    const float* bq2 = (const float*)d_in[7];
    const float* wk2 = (const float*)d_in[8];
    const float* bk2 = (const float*)d_in[9];
    const float* wdr = (const float*)d_in[10];  // [512,1536]
    const float* bdr = (const float*)d_in[11];
    float* out = (float*)d_out;                 // [16,512,P]

    float *mvT, *ffT, *Q1t, *K1t, *Q2t, *K2t, *S, *WRT, *WLT;
    cudaGetSymbolAddress((void**)&mvT, g_mvT);
    cudaGetSymbolAddress((void**)&ffT, g_ffT);
    cudaGetSymbolAddress((void**)&Q1t, g_Q1t);
    cudaGetSymbolAddress((void**)&K1t, g_K1t);
    cudaGetSymbolAddress((void**)&Q2t, g_Q2t);
    cudaGetSymbolAddress((void**)&K2t, g_K2t);
    cudaGetSymbolAddress((void**)&S,   g_S);
    cudaGetSymbolAddress((void**)&WRT, g_WRT);
    cudaGetSymbolAddress((void**)&WLT, g_WLT);

    cudaFuncSetAttribute(tfgemm<0, false>, cudaFuncAttributeMaxDynamicSharedMemorySize, SMEM_DYN);
    cudaFuncSetAttribute(tfgemm<1, false>, cudaFuncAttributeMaxDynamicSharedMemorySize, SMEM_DYN);
    cudaFuncSetAttribute(tfgemm<2, true>,  cudaFuncAttributeMaxDynamicSharedMemorySize, SMEM_DYN);

    const long long sMVT = (long long)Pn * CX_;
    const long long sFFT = (long long)Pn * CF_;
    const long long sHT  = (long long)Pn * HID_;
    const long long sS   = (long long)Pn * Pn;
    const long long sWRT = (long long)Pn * CF_;
    const long long sWLT = (long long)Pn * CX_;
    const long long sO   = (long long)OUT_ * Pn;

    // transposes -> K-major inputs
    transp<<<dim3(Pn / 32, CX_ / 32, 16), dim3(32, 8)>>>(mv, mvT, CX_);
    transp<<<dim3(Pn / 32, CF_ / 32, 4),  dim3(32, 8)>>>(ff, ffT, CF_);

    // projections: D[p,h] = sum_c X[p,c] * W[h,c] + b[h]
    tfgemm<1, false><<<dim3(2, 18, 16), NTHREADS, SMEM_DYN>>>(
        mvT, CX_, sMVT, 1,  wq1, CX_, 0LL, 1,  nullptr, nullptr, nullptr,
        bq1,  Q1t, HID_, sHT, CX_);
    tfgemm<1, false><<<dim3(2, 18, 4), NTHREADS, SMEM_DYN>>>(
        ffT, CF_, sFFT, 1,  wk1, CF_, 0LL, 1,  nullptr, nullptr, nullptr,
        bk1,  K1t, HID_, sHT, CF_);
    tfgemm<1, false><<<dim3(2, 18, 4), NTHREADS, SMEM_DYN>>>(
        ffT, CF_, sFFT, 1,  wq2, CF_, 0LL, 1,  nullptr, nullptr, nullptr,
        bq2,  Q2t, HID_, sHT, CF_);
    tfgemm<1, false><<<dim3(2, 18, 16), NTHREADS, SMEM_DYN>>>(
        mvT, CX_, sMVT, 1,  wk2, CX_, 0LL, 1,  nullptr, nullptr, nullptr,
        bk2,  K2t, HID_, sHT, CX_);

    // layer 1: S[p,q] = Q1t[p,:].K1t[q,:]; softmax; WRT[p,c] = S[p,:].ff[c,:]
    tfgemm<0, false><<<dim3(18, 18, 16), NTHREADS, SMEM_DYN>>>(
        Q1t, HID_, sHT, 1,  K1t, HID_, sHT, 4,  nullptr, nullptr, nullptr,
        nullptr,  S, Pn, sS, HID_);
    softmax_rows<<<dim3(Pn, BN_), 256>>>(S);
    tfgemm<0, false><<<dim3(2, 18, 16), NTHREADS, SMEM_DYN>>>(
        S, Pn, sS, 1,  ff, Pn, (long long)CF_ * Pn, 4,  nullptr, nullptr, nullptr,
        nullptr,  WRT, CF_, sWRT, Pn);

    // layer 2
    tfgemm<0, false><<<dim3(18, 18, 16), NTHREADS, SMEM_DYN>>>(
        Q2t, HID_, sHT, 4,  K2t, HID_, sHT, 1,  nullptr, nullptr, nullptr,
        nullptr,  S, Pn, sS, HID_);
    softmax_rows<<<dim3(Pn, BN_), 256>>>(S);
    tfgemm<0, false><<<dim3(4, 18, 16), NTHREADS, SMEM_DYN>>>(
        S, Pn, sS, 1,  mv, Pn, (long long)CX_ * Pn, 1,  nullptr, nullptr, nullptr,
        nullptr,  WLT, CX_, sWLT, Pn);

    // fused conv: out[o,p] = sum_f wdr[o,f] * featT[p,f] + bdr[o], K=1536
    tfgemm<2, true><<<dim3(18, 4, 16), NTHREADS, SMEM_DYN>>>(
        wdr, 1536, 0LL, 1,  mvT, 0, 0LL, 1,  WLT, ffT, WRT,
        bdr,  out, Pn, sO, 1536);
}